// round 4
// baseline (speedup 1.0000x reference)
#include <cuda_runtime.h>
#include <math.h>

// Problem shape (fixed by the dataset): xyz1 (16,2048,3), xyz2 (16,2048,3)
#define BB 16
#define NN 2048
#define MM 2048

constexpr float EPSv = 1e-9f;

// -------- device scratch (static globals: allocation-free per the rules) ----
__device__ float g_w[(size_t)BB * NN * MM];       // 268 MB, w' of current iteration
__device__ float g_remainL[BB * NN];
__device__ float g_remainR[BB * MM];
__device__ float g_sumr[BB * MM];                 // column sums of w'
__device__ float g_colcost[BB * MM];              // column sums of w'*sqrtd
__device__ float g_cons[BB * MM];
__device__ float g_rowS[BB * NN];                 // row sums s_i (0 => row's w' is all-zero)

__device__ __forceinline__ float ex2f(float x) {
    float y; asm("ex2.approx.ftz.f32 %0, %1;" : "=f"(y) : "f"(x)); return y;
}
__device__ __forceinline__ float sqrt_approx(float x) {
    float y; asm("sqrt.approx.ftz.f32 %0, %1;" : "=f"(y) : "f"(x)); return y;
}

// ---------------------------------------------------------------------------
__global__ void init_kernel(float* __restrict__ out, float initL, float initR) {
    int idx = blockIdx.x * blockDim.x + threadIdx.x;
    if (idx < BB * NN) { g_remainL[idx] = initL; g_rowS[idx] = 0.f; }
    if (idx < BB * MM) { g_remainR[idx] = initR; g_sumr[idx] = 0.f; g_colcost[idx] = 0.f; }
    if (idx < BB) out[idx] = 0.f;
}

// One iteration of the annealing loop. Identical control flow to the round-1
// passing kernel; the ONLY change is that sq/d2 are computed inline from the
// xyz coordinates instead of being read from a precomputed sqrtd matrix.
template <bool SKIP>
__global__ void __launch_bounds__(256) passA_kernel(
    const float* __restrict__ xyz1, const float* __restrict__ xyz2,
    float lvl2, int zerolvl, int first)
{
    const int b = blockIdx.y;
    const int warp = threadIdx.x >> 5, lane = threadIdx.x & 31;
    const int cbase = warp * 256 + lane * 8;
    const int row0 = blockIdx.x * 8;

    __shared__ float sm_red[16];
    __shared__ float sm_scale;
    __shared__ int   sm_flag;
    __shared__ float sm_oldS[8];

    // xyz2 points for this lane's 8 columns (registers)
    float x2[8], y2[8], z2[8];
    {
        const float* p2 = xyz2 + ((size_t)b * MM + cbase) * 3;
#pragma unroll
        for (int k = 0; k < 8; k++) {
            x2[k] = p2[3*k]; y2[k] = p2[3*k+1]; z2[k] = p2[3*k+2];
        }
    }

    float rr[8], cc[8];
    {
        const float4* p = (const float4*)(g_remainR + b * MM + cbase);
        float4 a = p[0], c4 = p[1];
        rr[0]=a.x; rr[1]=a.y; rr[2]=a.z; rr[3]=a.w;
        rr[4]=c4.x; rr[5]=c4.y; rr[6]=c4.z; rr[7]=c4.w;
    }
    if (!first) {
        const float4* p = (const float4*)(g_cons + b * MM + cbase);
        float4 a = p[0], c4 = p[1];
        cc[0]=a.x; cc[1]=a.y; cc[2]=a.z; cc[3]=a.w;
        cc[4]=c4.x; cc[5]=c4.y; cc[6]=c4.z; cc[7]=c4.w;
    } else {
#pragma unroll
        for (int k = 0; k < 8; k++) cc[k] = 0.f;
    }
    if (threadIdx.x < 8)
        sm_oldS[threadIdx.x] = first ? 0.f : g_rowS[b * NN + row0 + threadIdx.x];
    __syncthreads();

    float colsum[8], colcost[8];
#pragma unroll
    for (int k = 0; k < 8; k++) { colsum[k] = 0.f; colcost[k] = 0.f; }

    const float thr = SKIP ? (-126.0f / lvl2) : 3.0e38f;   // d2 < thr <=> exp arg > -126

    for (int r = 0; r < 8; r++) {
        const int i = row0 + r;
        const size_t base = ((size_t)(b * NN + i)) * MM + cbase;

        // phase0: remainL decrement from previous iteration's w' and cons
        float rdp = 0.f;
        if (!first && sm_oldS[r] != 0.f) {
            float4 wa = *(const float4*)(g_w + base);
            float4 wb = *(const float4*)(g_w + base + 4);
            rdp = wa.x*cc[0] + wa.y*cc[1] + wa.z*cc[2] + wa.w*cc[3]
                + wb.x*cc[4] + wb.y*cc[5] + wb.z*cc[6] + wb.w*cc[7];
        }

        // distances for this row (inline; broadcast loads of the row point hit L1)
        const float x1 = xyz1[((size_t)b * NN + i) * 3 + 0];
        const float y1 = xyz1[((size_t)b * NN + i) * 3 + 1];
        const float z1 = xyz1[((size_t)b * NN + i) * 3 + 2];
        float d2[8], sq[8];
#pragma unroll
        for (int k = 0; k < 8; k++) {
            float dx = x1 - x2[k], dy = y1 - y2[k], dz = z1 - z2[k];
            float dd = fmaf(dz, dz, fmaf(dy, dy, dx * dx));
            d2[k] = dd;
            sq[k] = sqrt_approx(dd);
        }

        // phase1: e and row sum
        float e[8];
        float srow = 0.f;
        if (zerolvl) {
#pragma unroll
            for (int k = 0; k < 8; k++) { e[k] = rr[k]; srow += e[k]; }
        } else {
            bool active = true;
            if (SKIP) {
                float mn = d2[0];
#pragma unroll
                for (int k = 1; k < 8; k++) mn = fminf(mn, d2[k]);
                active = __any_sync(0xffffffffu, mn < thr);
            }
            if (active) {
#pragma unroll
                for (int k = 0; k < 8; k++) {
                    e[k] = ex2f(lvl2 * d2[k]) * rr[k];
                    srow += e[k];
                }
            } else {
#pragma unroll
                for (int k = 0; k < 8; k++) e[k] = 0.f;
            }
        }

        // combined warp reduction of (rdec_partial, srow_partial)
#pragma unroll
        for (int off = 16; off > 0; off >>= 1) {
            rdp  += __shfl_down_sync(0xffffffffu, rdp,  off);
            srow += __shfl_down_sync(0xffffffffu, srow, off);
        }
        if (lane == 0) { sm_red[warp * 2] = rdp; sm_red[warp * 2 + 1] = srow; }
        __syncthreads();
        if (threadIdx.x == 0) {
            float rdec = 0.f, s = 0.f;
#pragma unroll
            for (int w2 = 0; w2 < 8; w2++) { rdec += sm_red[w2*2]; s += sm_red[w2*2+1]; }
            const int li = b * NN + i;
            float rl = fmaxf(g_remainL[li] - rdec, 0.f);
            g_remainL[li] = rl;
            g_rowS[li] = s;
            sm_scale = rl / (s + EPSv);
            sm_flag = (s == 0.f);
        }
        __syncthreads();

        // phase2: scale, store w', accumulate column sums (skip all-zero rows)
        if (!sm_flag) {
            const float scale = sm_scale;
            float w8[8];
#pragma unroll
            for (int k = 0; k < 8; k++) {
                float wv = e[k] * scale;
                w8[k] = wv;
                colsum[k]  += wv;
                colcost[k] += wv * sq[k];
            }
            *(float4*)(g_w + base)     = make_float4(w8[0], w8[1], w8[2], w8[3]);
            *(float4*)(g_w + base + 4) = make_float4(w8[4], w8[5], w8[6], w8[7]);
        }
    }

#pragma unroll
    for (int k = 0; k < 8; k++) atomicAdd(&g_sumr[b * MM + cbase + k], colsum[k]);
#pragma unroll
    for (int k = 0; k < 8; k++) atomicAdd(&g_colcost[b * MM + cbase + k], colcost[k]);
}

// Column saturation + remainR update + cost accumulation; also zeroes the
// column accumulators for the next iteration. One block per batch.
__global__ void cons_kernel(float* __restrict__ out) {
    const int b = blockIdx.x;
    float local = 0.f;
    for (int l = threadIdx.x; l < MM; l += 256) {
        const int idx = b * MM + l;
        float sr  = g_sumr[idx];
        float rrv = g_remainR[idx];
        float c = fminf(rrv / (sr + EPSv), 1.0f);
        g_cons[idx] = c;
        g_remainR[idx] = fmaxf(rrv - sr * c, 0.f);
        local += c * g_colcost[idx];
        g_sumr[idx] = 0.f;
        g_colcost[idx] = 0.f;
    }
    __shared__ float red[256];
    red[threadIdx.x] = local;
    __syncthreads();
    for (int s = 128; s > 0; s >>= 1) {
        if (threadIdx.x < s) red[threadIdx.x] += red[threadIdx.x + s];
        __syncthreads();
    }
    if (threadIdx.x == 0) out[b] += red[0];
}

// ---------------------------------------------------------------------------
extern "C" void kernel_launch(void* const* d_in, const int* in_sizes, int n_in,
                              void* d_out, int out_size) {
    (void)in_sizes; (void)n_in; (void)out_size;
    const float* xyz1 = (const float*)d_in[0];
    const float* xyz2 = (const float*)d_in[1];
    float* out = (float*)d_out;

    const float mx = (float)(NN > MM ? NN : MM);
    init_kernel<<<(BB * MM + 255) / 256, 256>>>(out, mx / (float)NN, mx / (float)MM);

    const float LOG2E = 1.4426950408889634f;
    int first = 1;
    for (int j = 7; j >= -2; --j) {
        float level = (j == -2) ? 0.f : -powf(4.f, (float)j);
        float lvl2 = level * LOG2E;
        int zerolvl = (level == 0.f) ? 1 : 0;
        dim3 grid(NN / 8, BB);
        if (level < -200.f)
            passA_kernel<true><<<grid, 256>>>(xyz1, xyz2, lvl2, zerolvl, first);
        else
            passA_kernel<false><<<grid, 256>>>(xyz1, xyz2, lvl2, zerolvl, first);
        cons_kernel<<<BB, 256>>>(out);
        first = 0;
    }
}

// round 6
// speedup vs baseline: 1.2494x; 1.2494x over previous
#include <cuda_runtime.h>
#include <math.h>

// Problem shape (fixed by the dataset): xyz1 (16,2048,3), xyz2 (16,2048,3)
#define BB 16
#define NN 2048
#define MM 2048

constexpr float EPSv = 1e-9f;

// -------- device scratch (static globals: allocation-free per the rules) ----
__device__ float g_w[(size_t)BB * NN * MM];       // 268 MB, w' of current iteration
__device__ float g_remainL[BB * NN];
__device__ float g_remainR[BB * MM];
__device__ float g_sumr[BB * MM];                 // column sums of w'
__device__ float g_colcost[BB * MM];              // column sums of w'*sqrt(d2)
__device__ float g_cons[BB * MM];
__device__ float g_rowS[BB * NN];                 // row sums s_i (0 => stored w row invalid/zero)

__device__ __forceinline__ float ex2f(float x) {
    float y; asm("ex2.approx.ftz.f32 %0, %1;" : "=f"(y) : "f"(x)); return y;
}
__device__ __forceinline__ float sqrt_approx(float x) {
    float y; asm("sqrt.approx.ftz.f32 %0, %1;" : "=f"(y) : "f"(x)); return y;
}

// ---------------------------------------------------------------------------
__global__ void init_kernel(float* __restrict__ out, float initL, float initR) {
    int idx = blockIdx.x * blockDim.x + threadIdx.x;
    if (idx < BB * NN) { g_remainL[idx] = initL; g_rowS[idx] = 0.f; }
    if (idx < BB * MM) { g_remainR[idx] = initR; g_sumr[idx] = 0.f; g_colcost[idx] = 0.f; }
    if (idx < BB) out[idx] = 0.f;
}

// One annealing iteration. Block = 8 rows x 2048 cols; warp owns a 256-col
// slab, lane owns 8 consecutive cols. Two barriers per block total:
//   loop1: per-row partials (rdp from stored w_old*cons; srow from exp) - no syncs
//   reduce: shfl 16 values, smem, barrier, threads 0..7 finalize rows, barrier
//   loop2: recompute e (bit-identical), scale, store w, column accumulators
template <bool SKIP>
__global__ void __launch_bounds__(256) passA_kernel(
    const float* __restrict__ xyz1, const float* __restrict__ xyz2,
    float lvl2, int zerolvl, int first, int last)
{
    const int b = blockIdx.y;
    const int row0 = blockIdx.x * 8;
    const int warp = threadIdx.x >> 5, lane = threadIdx.x & 31;
    const int cbase = warp * 256 + lane * 8;
    const int t = threadIdx.x;

    __shared__ float sm_srow[8][8];   // [warp][row]
    __shared__ float sm_rdp[8][8];    // [warp][row]
    __shared__ float sm_scale[8];
    __shared__ int   sm_act[8];

    // xyz2 points for this lane's 8 columns (registers)
    float x2[8], y2[8], z2[8];
    {
        const float* p2 = xyz2 + ((size_t)b * MM + cbase) * 3;
#pragma unroll
        for (int k = 0; k < 8; k++) {
            x2[k] = p2[3*k]; y2[k] = p2[3*k+1]; z2[k] = p2[3*k+2];
        }
    }

    float rr[8], cc[8];
    {
        const float4* p = (const float4*)(g_remainR + b * MM + cbase);
        float4 a = p[0], c4 = p[1];
        rr[0]=a.x; rr[1]=a.y; rr[2]=a.z; rr[3]=a.w;
        rr[4]=c4.x; rr[5]=c4.y; rr[6]=c4.z; rr[7]=c4.w;
    }
    if (!first) {
        const float4* p = (const float4*)(g_cons + b * MM + cbase);
        float4 a = p[0], c4 = p[1];
        cc[0]=a.x; cc[1]=a.y; cc[2]=a.z; cc[3]=a.w;
        cc[4]=c4.x; cc[5]=c4.y; cc[6]=c4.z; cc[7]=c4.w;
    } else {
#pragma unroll
        for (int k = 0; k < 8; k++) cc[k] = 0.f;
    }

    const float thr = SKIP ? (-126.0f / lvl2) : 3.0e38f;   // d2 < thr <=> exp arg > -126

    // ---- loop 1: per-row partial sums, no barriers --------------------------
    float srowP[8], rdpP[8];
#pragma unroll
    for (int r = 0; r < 8; r++) {
        const int i = row0 + r;
        const size_t base = ((size_t)(b * NN + i)) * MM + cbase;

        float rdp = 0.f;
        if (!first && g_rowS[b * NN + i] != 0.f) {   // FIX: batch offset
            float4 wa = *(const float4*)(g_w + base);
            float4 wb = *(const float4*)(g_w + base + 4);
            rdp = wa.x*cc[0] + wa.y*cc[1] + wa.z*cc[2] + wa.w*cc[3]
                + wb.x*cc[4] + wb.y*cc[5] + wb.z*cc[6] + wb.w*cc[7];
        }

        float srow = 0.f;
        if (zerolvl) {
#pragma unroll
            for (int k = 0; k < 8; k++) srow += rr[k];
        } else {
            const float x1 = xyz1[((size_t)b * NN + i) * 3 + 0];
            const float y1 = xyz1[((size_t)b * NN + i) * 3 + 1];
            const float z1 = xyz1[((size_t)b * NN + i) * 3 + 2];
            float d2[8];
            float mn = 3.0e38f;
#pragma unroll
            for (int k = 0; k < 8; k++) {
                float dx = x1 - x2[k], dy = y1 - y2[k], dz = z1 - z2[k];
                float dd = fmaf(dz, dz, fmaf(dy, dy, dx * dx));
                d2[k] = dd;
                mn = fminf(mn, dd);
            }
            bool active = true;
            if (SKIP) active = __any_sync(0xffffffffu, mn < thr);
            if (active) {
#pragma unroll
                for (int k = 0; k < 8; k++)
                    srow += ex2f(lvl2 * d2[k]) * rr[k];
            }
        }
        srowP[r] = srow;
        rdpP[r]  = rdp;
    }

    // ---- batched reduction: one shfl tree for all 16 partials ---------------
#pragma unroll
    for (int off = 16; off > 0; off >>= 1) {
#pragma unroll
        for (int r = 0; r < 8; r++) {
            srowP[r] += __shfl_xor_sync(0xffffffffu, srowP[r], off);
            rdpP[r]  += __shfl_xor_sync(0xffffffffu, rdpP[r],  off);
        }
    }
    if (lane == 0) {
#pragma unroll
        for (int r = 0; r < 8; r++) {
            sm_srow[warp][r] = srowP[r];
            sm_rdp[warp][r]  = rdpP[r];
        }
    }
    __syncthreads();

    if (t < 8) {                      // thread t finalizes row t
        float s = 0.f, rdec = 0.f;
#pragma unroll
        for (int w2 = 0; w2 < 8; w2++) { s += sm_srow[w2][t]; rdec += sm_rdp[w2][t]; }
        const int li = b * NN + row0 + t;
        float rl = fmaxf(g_remainL[li] - rdec, 0.f);
        g_remainL[li] = rl;
        g_rowS[li] = s;
        sm_scale[t] = rl / (s + EPSv);
        sm_act[t] = (s != 0.f) ? 1 : 0;
    }
    __syncthreads();

    // ---- loop 2: recompute e (bit-identical), scale, store, column sums -----
    float colsum[8], colcost[8];
#pragma unroll
    for (int k = 0; k < 8; k++) { colsum[k] = 0.f; colcost[k] = 0.f; }

    for (int r = 0; r < 8; r++) {
        if (!sm_act[r]) continue;
        const int i = row0 + r;
        const size_t base = ((size_t)(b * NN + i)) * MM + cbase;
        const float scale = sm_scale[r];
        const float x1 = xyz1[((size_t)b * NN + i) * 3 + 0];
        const float y1 = xyz1[((size_t)b * NN + i) * 3 + 1];
        const float z1 = xyz1[((size_t)b * NN + i) * 3 + 2];

        float w8[8];
#pragma unroll
        for (int k = 0; k < 8; k++) {
            float dx = x1 - x2[k], dy = y1 - y2[k], dz = z1 - z2[k];
            float dd = fmaf(dz, dz, fmaf(dy, dy, dx * dx));
            float e = zerolvl ? rr[k] : ex2f(lvl2 * dd) * rr[k];
            float wv = e * scale;
            w8[k] = wv;
            colsum[k] += wv;
            colcost[k] = fmaf(wv, sqrt_approx(dd), colcost[k]);
        }
        if (!last) {
            *(float4*)(g_w + base)     = make_float4(w8[0], w8[1], w8[2], w8[3]);
            *(float4*)(g_w + base + 4) = make_float4(w8[4], w8[5], w8[6], w8[7]);
        }
    }

#pragma unroll
    for (int k = 0; k < 8; k++) atomicAdd(&g_sumr[b * MM + cbase + k], colsum[k]);
#pragma unroll
    for (int k = 0; k < 8; k++) atomicAdd(&g_colcost[b * MM + cbase + k], colcost[k]);
}

// Column saturation + remainR update + cost accumulation; zeroes accumulators.
__global__ void __launch_bounds__(1024) cons_kernel(float* __restrict__ out) {
    const int b = blockIdx.x;
    float local = 0.f;
    for (int l = threadIdx.x; l < MM; l += 1024) {
        const int idx = b * MM + l;
        float sr  = g_sumr[idx];
        float rrv = g_remainR[idx];
        float c = fminf(rrv / (sr + EPSv), 1.0f);
        g_cons[idx] = c;
        g_remainR[idx] = fmaxf(rrv - sr * c, 0.f);
        local += c * g_colcost[idx];
        g_sumr[idx] = 0.f;
        g_colcost[idx] = 0.f;
    }
    __shared__ float red[1024];
    red[threadIdx.x] = local;
    __syncthreads();
    for (int s = 512; s > 0; s >>= 1) {
        if (threadIdx.x < s) red[threadIdx.x] += red[threadIdx.x + s];
        __syncthreads();
    }
    if (threadIdx.x == 0) out[b] += red[0];
}

// ---------------------------------------------------------------------------
extern "C" void kernel_launch(void* const* d_in, const int* in_sizes, int n_in,
                              void* d_out, int out_size) {
    (void)in_sizes; (void)n_in; (void)out_size;
    const float* xyz1 = (const float*)d_in[0];
    const float* xyz2 = (const float*)d_in[1];
    float* out = (float*)d_out;

    const float mx = (float)(NN > MM ? NN : MM);
    init_kernel<<<(BB * MM + 255) / 256, 256>>>(out, mx / (float)NN, mx / (float)MM);

    const float LOG2E = 1.4426950408889634f;
    int first = 1;
    for (int j = 7; j >= -2; --j) {
        float level = (j == -2) ? 0.f : -powf(4.f, (float)j);
        float lvl2 = level * LOG2E;
        int zerolvl = (level == 0.f) ? 1 : 0;
        int last = (j == -2) ? 1 : 0;
        dim3 grid(NN / 8, BB);
        if (level < -200.f)
            passA_kernel<true><<<grid, 256>>>(xyz1, xyz2, lvl2, zerolvl, first, last);
        else
            passA_kernel<false><<<grid, 256>>>(xyz1, xyz2, lvl2, zerolvl, first, last);
        cons_kernel<<<BB, 1024>>>(out);
        first = 0;
    }
}

// round 7
// speedup vs baseline: 2.7667x; 2.2144x over previous
#include <cuda_runtime.h>
#include <math.h>

// Problem shape (fixed by the dataset): xyz1 (16,2048,3), xyz2 (16,2048,3)
#define BB 16
#define NN 2048
#define MM 2048
#define RPW 8                 // rows per warp
#define WPB 8                 // warps per block (256 threads)
#define ROWS_PB (RPW * WPB)   // 64 rows per block

constexpr float EPSv = 1e-9f;

// -------- device scratch (static globals: allocation-free per the rules) ----
__device__ float g_w[(size_t)BB * NN * MM];       // 268 MB, w' of current iteration
__device__ float g_remainL[BB * NN];
__device__ float g_remainR[BB * MM];
__device__ float g_sumr[BB * MM];                 // column sums of w'
__device__ float g_colcost[BB * MM];              // column sums of w'*sqrt(d2)
__device__ float g_cons[BB * MM];
__device__ float g_rowS[BB * NN];                 // row sums s_i (0 => stored w row invalid/zero)

__device__ __forceinline__ float ex2f(float x) {
    float y; asm("ex2.approx.ftz.f32 %0, %1;" : "=f"(y) : "f"(x)); return y;
}
__device__ __forceinline__ float sqrt_approx(float x) {
    float y; asm("sqrt.approx.ftz.f32 %0, %1;" : "=f"(y) : "f"(x)); return y;
}

// ---------------------------------------------------------------------------
__global__ void init_kernel(float* __restrict__ out, float initL, float initR) {
    int idx = blockIdx.x * blockDim.x + threadIdx.x;
    if (idx < BB * NN) { g_remainL[idx] = initL; g_rowS[idx] = 0.f; }
    if (idx < BB * MM) { g_remainR[idx] = initR; g_sumr[idx] = 0.f; g_colcost[idx] = 0.f; }
    if (idx < BB) out[idx] = 0.f;
}

#define MODE_NORM 0
#define MODE_SKIP 1
#define MODE_ZERO 2

// One annealing iteration, warp-autonomous:
//  - block stages xyz2 (SoA) + remainR + cons into smem (ONE barrier)
//  - each warp owns 8 complete rows x all 2048 cols (lane = col-in-chunk)
//  - loop1: per-row partials (rdp from stored w_old*cons; srow from exp)
//  - warp shfl reduce only, lane0 finalizes rows (remainL, rowS)
//  - loop2: recompute e (bit-identical under FTZ), scale, store w,
//           per-lane column partials over 8 rows -> 2 REDG atomics per chunk
template <int MODE>
__global__ void __launch_bounds__(256) passA_kernel(
    const float* __restrict__ xyz1, const float* __restrict__ xyz2,
    float lvl2, float thr, int first, int last)
{
    __shared__ float smx[MM], smy[MM], smz[MM], smrr[MM], smcc[MM];

    const int b = blockIdx.y;
    const int t = threadIdx.x, warp = t >> 5, lane = t & 31;
    const int row0 = blockIdx.x * ROWS_PB + warp * RPW;

    // stage column data (coalesced-ish; one barrier total)
    for (int idx = t; idx < MM; idx += 256) {
        const float* p2 = xyz2 + ((size_t)b * MM + idx) * 3;
        smx[idx] = p2[0]; smy[idx] = p2[1]; smz[idx] = p2[2];
        smrr[idx] = g_remainR[b * MM + idx];
        smcc[idx] = first ? 0.f : g_cons[b * MM + idx];
    }
    __syncthreads();

    // this warp's 8 row points + state
    float x1[RPW], y1[RPW], z1[RPW], srow[RPW], rdp[RPW];
    unsigned prevmask = 0;
#pragma unroll
    for (int r = 0; r < RPW; r++) {
        const float* p1 = xyz1 + ((size_t)b * NN + row0 + r) * 3;
        x1[r] = p1[0]; y1[r] = p1[1]; z1[r] = p1[2];
        srow[r] = 0.f; rdp[r] = 0.f;
        if (!first && g_rowS[b * NN + row0 + r] != 0.f) prevmask |= (1u << r);
    }

    float* wbase = g_w + ((size_t)(b * NN + row0)) * MM;

    // ---- loop 1: row-sum partials + deferred remainL dot product ------------
    float racc = 0.f;                        // ZERO mode: sum(rr) shared by all rows
    for (int c = 0; c < MM; c += 32) {
        const int col = c + lane;

        if (prevmask) {
            const float lcc = smcc[col];
#pragma unroll
            for (int r = 0; r < RPW; r++)
                if (prevmask & (1u << r))
                    rdp[r] = fmaf(wbase[(size_t)r * MM + col], lcc, rdp[r]);
        }

        if (MODE == MODE_ZERO) {
            racc += smrr[col];
        } else {
            const float bx = smx[col], by = smy[col], bz = smz[col];
            const float lrr = smrr[col];
            float dd[RPW];
            float mn = 3.0e38f;
#pragma unroll
            for (int r = 0; r < RPW; r++) {
                float dx = x1[r] - bx, dy = y1[r] - by, dz = z1[r] - bz;
                dd[r] = fmaf(dz, dz, fmaf(dy, dy, dx * dx));
                if (MODE == MODE_SKIP) mn = fminf(mn, dd[r]);
            }
            bool active = true;
            if (MODE == MODE_SKIP) active = __any_sync(0xffffffffu, mn < thr);
            if (active) {
#pragma unroll
                for (int r = 0; r < RPW; r++)
                    srow[r] = fmaf(ex2f(lvl2 * dd[r]), lrr, srow[r]);
            }
        }
    }
    if (MODE == MODE_ZERO) {
#pragma unroll
        for (int r = 0; r < RPW; r++) srow[r] = racc;
    }

    // ---- warp-only reduction (butterfly -> all lanes hold the sums) ---------
#pragma unroll
    for (int off = 16; off > 0; off >>= 1) {
#pragma unroll
        for (int r = 0; r < RPW; r++) {
            srow[r] += __shfl_xor_sync(0xffffffffu, srow[r], off);
            rdp[r]  += __shfl_xor_sync(0xffffffffu, rdp[r],  off);
        }
    }

    float scale[RPW];
    unsigned actmask = 0;
#pragma unroll
    for (int r = 0; r < RPW; r++) {
        const int li = b * NN + row0 + r;
        float rl = fmaxf(g_remainL[li] - rdp[r], 0.f);
        scale[r] = rl / (srow[r] + EPSv);
        if (srow[r] != 0.f) actmask |= (1u << r);
        if (lane == 0) { g_remainL[li] = rl; g_rowS[li] = srow[r]; }
    }

    if (!actmask) return;   // whole warp: nothing to store/accumulate

    // ---- loop 2: recompute e, scale, store w, column partials ---------------
    for (int c = 0; c < MM; c += 32) {
        const int col = c + lane;
        const float bx = smx[col], by = smy[col], bz = smz[col];
        const float lrr = smrr[col];
        float csum = 0.f, ccost = 0.f;
#pragma unroll
        for (int r = 0; r < RPW; r++) {
            if (actmask & (1u << r)) {
                float dx = x1[r] - bx, dy = y1[r] - by, dz = z1[r] - bz;
                float dd = fmaf(dz, dz, fmaf(dy, dy, dx * dx));
                float e = (MODE == MODE_ZERO) ? lrr : ex2f(lvl2 * dd) * lrr;
                float wv = e * scale[r];
                csum += wv;
                ccost = fmaf(wv, sqrt_approx(dd), ccost);
                if (!last) wbase[(size_t)r * MM + col] = wv;
            }
        }
        atomicAdd(&g_sumr[b * MM + col], csum);
        atomicAdd(&g_colcost[b * MM + col], ccost);
    }
}

// Column saturation + remainR update + cost accumulation; zeroes accumulators.
__global__ void __launch_bounds__(1024) cons_kernel(float* __restrict__ out) {
    const int b = blockIdx.x;
    float local = 0.f;
    for (int l = threadIdx.x; l < MM; l += 1024) {
        const int idx = b * MM + l;
        float sr  = g_sumr[idx];
        float rrv = g_remainR[idx];
        float c = fminf(rrv / (sr + EPSv), 1.0f);
        g_cons[idx] = c;
        g_remainR[idx] = fmaxf(rrv - sr * c, 0.f);
        local += c * g_colcost[idx];
        g_sumr[idx] = 0.f;
        g_colcost[idx] = 0.f;
    }
    __shared__ float red[1024];
    red[threadIdx.x] = local;
    __syncthreads();
    for (int s = 512; s > 0; s >>= 1) {
        if (threadIdx.x < s) red[threadIdx.x] += red[threadIdx.x + s];
        __syncthreads();
    }
    if (threadIdx.x == 0) out[b] += red[0];
}

// ---------------------------------------------------------------------------
extern "C" void kernel_launch(void* const* d_in, const int* in_sizes, int n_in,
                              void* d_out, int out_size) {
    (void)in_sizes; (void)n_in; (void)out_size;
    const float* xyz1 = (const float*)d_in[0];
    const float* xyz2 = (const float*)d_in[1];
    float* out = (float*)d_out;

    const float mx = (float)(NN > MM ? NN : MM);
    init_kernel<<<(BB * MM + 255) / 256, 256>>>(out, mx / (float)NN, mx / (float)MM);

    const float LOG2E = 1.4426950408889634f;
    int first = 1;
    dim3 grid(NN / ROWS_PB, BB);   // (32, 16) = 512 blocks
    for (int j = 7; j >= -2; --j) {
        float level = (j == -2) ? 0.f : -powf(4.f, (float)j);
        float lvl2 = level * LOG2E;
        int last = (j == -2) ? 1 : 0;

        if (j == -2) {
            passA_kernel<MODE_ZERO><<<grid, 256>>>(xyz1, xyz2, 0.f, 0.f, first, last);
        } else if (level < -200.f) {
            float thr = -126.0f / lvl2;
            passA_kernel<MODE_SKIP><<<grid, 256>>>(xyz1, xyz2, lvl2, thr, first, last);
        } else {
            passA_kernel<MODE_NORM><<<grid, 256>>>(xyz1, xyz2, lvl2, 0.f, first, last);
        }
        cons_kernel<<<BB, 1024>>>(out);
        first = 0;
    }
}

// round 8
// speedup vs baseline: 2.8191x; 1.0189x over previous
#include <cuda_runtime.h>
#include <math.h>

// Problem shape (fixed by the dataset): xyz1 (16,2048,3), xyz2 (16,2048,3)
#define BB 16
#define NN 2048
#define MM 2048
#define RPW 4                 // rows per warp (reduced for register pressure / occupancy)
#define WPB 8                 // warps per block (256 threads)
#define ROWS_PB (RPW * WPB)   // 32 rows per block

constexpr float EPSv = 1e-9f;

// -------- device scratch (static globals: allocation-free per the rules) ----
__device__ float g_w[(size_t)BB * NN * MM];       // 268 MB, w' of current iteration
__device__ float g_remainL[BB * NN];
__device__ float g_remainR[BB * MM];
__device__ float g_sumr[BB * MM];                 // column sums of w'
__device__ float g_colcost[BB * MM];              // column sums of w'*sqrt(d2)
__device__ float g_cons[BB * MM];
__device__ float g_rowS[BB * NN];                 // row sums s_i (0 => stored w row invalid/zero)

__device__ __forceinline__ float ex2f(float x) {
    float y; asm("ex2.approx.ftz.f32 %0, %1;" : "=f"(y) : "f"(x)); return y;
}
__device__ __forceinline__ float sqrt_approx(float x) {
    float y; asm("sqrt.approx.ftz.f32 %0, %1;" : "=f"(y) : "f"(x)); return y;
}

// ---------------------------------------------------------------------------
__global__ void init_kernel(float* __restrict__ out, float initL, float initR) {
    int idx = blockIdx.x * blockDim.x + threadIdx.x;
    if (idx < BB * NN) { g_remainL[idx] = initL; g_rowS[idx] = 0.f; }
    if (idx < BB * MM) { g_remainR[idx] = initR; g_sumr[idx] = 0.f; g_colcost[idx] = 0.f; }
    if (idx < BB) out[idx] = 0.f;
}

#define MODE_NORM 0
#define MODE_SKIP 1
#define MODE_ZERO 2

// One annealing iteration, warp-autonomous (identical state machine to R7;
// only RPW/grid changed for occupancy):
//  - block stages xyz2 (SoA) + remainR + cons into smem (ONE barrier)
//  - each warp owns RPW complete rows x all 2048 cols
//  - loop1: per-row partials (rdp from stored w_old*cons; srow from exp)
//  - warp shfl reduce only; lane0 writes remainL/rowS
//  - loop2: recompute e (bit-identical under FTZ), scale, store w,
//           per-lane column partials -> 2 atomics per chunk
template <int MODE>
__global__ void __launch_bounds__(256, 5) passA_kernel(
    const float* __restrict__ xyz1, const float* __restrict__ xyz2,
    float lvl2, float thr, int first, int last)
{
    __shared__ float smx[MM], smy[MM], smz[MM], smrr[MM], smcc[MM];

    const int b = blockIdx.y;
    const int t = threadIdx.x, warp = t >> 5, lane = t & 31;
    const int row0 = blockIdx.x * ROWS_PB + warp * RPW;

    // stage column data (one barrier total)
    for (int idx = t; idx < MM; idx += 256) {
        const float* p2 = xyz2 + ((size_t)b * MM + idx) * 3;
        smx[idx] = p2[0]; smy[idx] = p2[1]; smz[idx] = p2[2];
        smrr[idx] = g_remainR[b * MM + idx];
        smcc[idx] = first ? 0.f : g_cons[b * MM + idx];
    }
    __syncthreads();

    // this warp's rows + state
    float x1[RPW], y1[RPW], z1[RPW], srow[RPW], rdp[RPW];
    unsigned prevmask = 0;
#pragma unroll
    for (int r = 0; r < RPW; r++) {
        const float* p1 = xyz1 + ((size_t)b * NN + row0 + r) * 3;
        x1[r] = p1[0]; y1[r] = p1[1]; z1[r] = p1[2];
        srow[r] = 0.f; rdp[r] = 0.f;
        if (!first && g_rowS[b * NN + row0 + r] != 0.f) prevmask |= (1u << r);
    }

    float* wbase = g_w + ((size_t)(b * NN + row0)) * MM;

    // ---- loop 1: row-sum partials + deferred remainL dot product ------------
    float racc = 0.f;                        // ZERO mode: sum(rr) shared by all rows
    for (int c = 0; c < MM; c += 32) {
        const int col = c + lane;

        if (prevmask) {
            const float lcc = smcc[col];
#pragma unroll
            for (int r = 0; r < RPW; r++)
                if (prevmask & (1u << r))
                    rdp[r] = fmaf(wbase[(size_t)r * MM + col], lcc, rdp[r]);
        }

        if (MODE == MODE_ZERO) {
            racc += smrr[col];
        } else {
            const float bx = smx[col], by = smy[col], bz = smz[col];
            float dd[RPW];
            float mn = 3.0e38f;
#pragma unroll
            for (int r = 0; r < RPW; r++) {
                float dx = x1[r] - bx, dy = y1[r] - by, dz = z1[r] - bz;
                dd[r] = fmaf(dz, dz, fmaf(dy, dy, dx * dx));
                if (MODE == MODE_SKIP) mn = fminf(mn, dd[r]);
            }
            bool active = true;
            if (MODE == MODE_SKIP) active = __any_sync(0xffffffffu, mn < thr);
            if (active) {
                const float lrr = smrr[col];
#pragma unroll
                for (int r = 0; r < RPW; r++)
                    srow[r] = fmaf(ex2f(lvl2 * dd[r]), lrr, srow[r]);
            }
        }
    }
    if (MODE == MODE_ZERO) {
#pragma unroll
        for (int r = 0; r < RPW; r++) srow[r] = racc;
    }

    // ---- warp-only reduction (butterfly -> all lanes hold the sums) ---------
#pragma unroll
    for (int off = 16; off > 0; off >>= 1) {
#pragma unroll
        for (int r = 0; r < RPW; r++) {
            srow[r] += __shfl_xor_sync(0xffffffffu, srow[r], off);
            rdp[r]  += __shfl_xor_sync(0xffffffffu, rdp[r],  off);
        }
    }

    float scale[RPW];
    unsigned actmask = 0;
#pragma unroll
    for (int r = 0; r < RPW; r++) {
        const int li = b * NN + row0 + r;
        float rl = fmaxf(g_remainL[li] - rdp[r], 0.f);
        scale[r] = rl / (srow[r] + EPSv);
        if (srow[r] != 0.f) actmask |= (1u << r);
        if (lane == 0) { g_remainL[li] = rl; g_rowS[li] = srow[r]; }
    }

    if (!actmask) return;   // whole warp: nothing to store/accumulate

    // ---- loop 2: recompute e, scale, store w, column partials ---------------
    for (int c = 0; c < MM; c += 32) {
        const int col = c + lane;
        const float bx = smx[col], by = smy[col], bz = smz[col];
        const float lrr = smrr[col];
        float csum = 0.f, ccost = 0.f;
#pragma unroll
        for (int r = 0; r < RPW; r++) {
            if (actmask & (1u << r)) {
                float dx = x1[r] - bx, dy = y1[r] - by, dz = z1[r] - bz;
                float dd = fmaf(dz, dz, fmaf(dy, dy, dx * dx));
                float e = (MODE == MODE_ZERO) ? lrr : ex2f(lvl2 * dd) * lrr;
                float wv = e * scale[r];
                csum += wv;
                ccost = fmaf(wv, sqrt_approx(dd), ccost);
                if (!last) wbase[(size_t)r * MM + col] = wv;
            }
        }
        atomicAdd(&g_sumr[b * MM + col], csum);
        atomicAdd(&g_colcost[b * MM + col], ccost);
    }
}

// Column saturation + remainR update + cost accumulation; zeroes accumulators.
// Parallelized: grid (MM/256, BB), block partials atomically added to out[b].
__global__ void __launch_bounds__(256) cons_kernel(float* __restrict__ out) {
    const int b = blockIdx.y;
    const int l = blockIdx.x * 256 + threadIdx.x;
    const int idx = b * MM + l;

    float sr  = g_sumr[idx];
    float rrv = g_remainR[idx];
    float c = fminf(rrv / (sr + EPSv), 1.0f);
    g_cons[idx] = c;
    g_remainR[idx] = fmaxf(rrv - sr * c, 0.f);
    float local = c * g_colcost[idx];
    g_sumr[idx] = 0.f;
    g_colcost[idx] = 0.f;

#pragma unroll
    for (int off = 16; off > 0; off >>= 1)
        local += __shfl_xor_sync(0xffffffffu, local, off);

    __shared__ float red[8];
    const int warp = threadIdx.x >> 5, lane = threadIdx.x & 31;
    if (lane == 0) red[warp] = local;
    __syncthreads();
    if (threadIdx.x == 0) {
        float s = 0.f;
#pragma unroll
        for (int w = 0; w < 8; w++) s += red[w];
        atomicAdd(&out[b], s);
    }
}

// ---------------------------------------------------------------------------
extern "C" void kernel_launch(void* const* d_in, const int* in_sizes, int n_in,
                              void* d_out, int out_size) {
    (void)in_sizes; (void)n_in; (void)out_size;
    const float* xyz1 = (const float*)d_in[0];
    const float* xyz2 = (const float*)d_in[1];
    float* out = (float*)d_out;

    const float mx = (float)(NN > MM ? NN : MM);
    init_kernel<<<(BB * MM + 255) / 256, 256>>>(out, mx / (float)NN, mx / (float)MM);

    const float LOG2E = 1.4426950408889634f;
    int first = 1;
    dim3 grid(NN / ROWS_PB, BB);     // (64, 16) = 1024 blocks
    dim3 cgrid(MM / 256, BB);        // (8, 16) = 128 blocks
    for (int j = 7; j >= -2; --j) {
        float level = (j == -2) ? 0.f : -powf(4.f, (float)j);
        float lvl2 = level * LOG2E;
        int last = (j == -2) ? 1 : 0;

        if (j == -2) {
            passA_kernel<MODE_ZERO><<<grid, 256>>>(xyz1, xyz2, 0.f, 0.f, first, last);
        } else if (level < -200.f) {
            float thr = -126.0f / lvl2;
            passA_kernel<MODE_SKIP><<<grid, 256>>>(xyz1, xyz2, lvl2, thr, first, last);
        } else {
            passA_kernel<MODE_NORM><<<grid, 256>>>(xyz1, xyz2, lvl2, 0.f, first, last);
        }
        cons_kernel<<<cgrid, 256>>>(out);
        first = 0;
    }
}

// round 9
// speedup vs baseline: 5.0542x; 1.7928x over previous
#include <cuda_runtime.h>
#include <math.h>

// Problem shape (fixed by the dataset): xyz1 (16,2048,3), xyz2 (16,2048,3)
#define BB 16
#define NN 2048
#define MM 2048
#define RPW 4                 // rows per warp
#define WPB 8                 // warps per block (256 threads)
#define ROWS_PB (RPW * WPB)   // 32 rows per block

constexpr float EPSv = 1e-9f;

// -------- device scratch (vectors only; NO matrix scratch at all) -----------
__device__ float g_remainL[BB * NN];
__device__ float g_scaleP[BB * NN];   // scale_i of previous iteration (0 if row sum was 0)
__device__ float g_remainR[BB * MM];
__device__ float g_ccrr[BB * MM];     // cons * remainR_prev of previous iteration
__device__ float g_sumr[BB * MM];     // column sums of w'
__device__ float g_colcost[BB * MM];  // column sums of w'*sqrt(d2)

__device__ __forceinline__ float ex2f(float x) {
    float y; asm("ex2.approx.ftz.f32 %0, %1;" : "=f"(y) : "f"(x)); return y;
}
__device__ __forceinline__ float sqrt_approx(float x) {
    float y; asm("sqrt.approx.ftz.f32 %0, %1;" : "=f"(y) : "f"(x)); return y;
}

// ---------------------------------------------------------------------------
__global__ void init_kernel(float* __restrict__ out, float initL, float initR) {
    int idx = blockIdx.x * blockDim.x + threadIdx.x;
    if (idx < BB * NN) { g_remainL[idx] = initL; g_scaleP[idx] = 0.f; }
    if (idx < BB * MM) { g_remainR[idx] = initR; g_ccrr[idx] = 0.f;
                         g_sumr[idx] = 0.f; g_colcost[idx] = 0.f; }
    if (idx < BB) out[idx] = 0.f;
}

#define MODE_NORM 0
#define MODE_SKIP 1
#define MODE_ZERO 2

// One annealing iteration, warp-autonomous, ZERO matrix traffic:
//  - block stages xyz2 (SoA) + remainR + ccrr into smem (ONE barrier)
//  - each warp owns RPW rows x all 2048 cols; d2 computed once per pair,
//    used for BOTH the new-level exp (row sum) and the old-level exp
//    (deferred remainL decrement: rdec = scaleP * sum(exp(l2old*d2)*ccrr)).
//    FTZ underflow makes the recomputed old-level values bit-identical to
//    the previous iteration's e (vote-skipped blocks underflow to exact 0).
//  - warp shfl reduce; lane0 writes remainL/scaleP
//  - loop2: recompute e, scale, per-lane column partials -> 2 atomics/chunk
template <int MODE>
__global__ void __launch_bounds__(256, 5) passA_kernel(
    const float* __restrict__ xyz1, const float* __restrict__ xyz2,
    float l2new, float l2old, float thrN, float thrO)
{
    __shared__ float smx[MM], smy[MM], smz[MM], smrr[MM], smcr[MM];

    const int b = blockIdx.y;
    const int t = threadIdx.x, warp = t >> 5, lane = t & 31;
    const int row0 = blockIdx.x * ROWS_PB + warp * RPW;

    // stage column data (one barrier total)
    for (int idx = t; idx < MM; idx += 256) {
        const float* p2 = xyz2 + ((size_t)b * MM + idx) * 3;
        smx[idx] = p2[0]; smy[idx] = p2[1]; smz[idx] = p2[2];
        smrr[idx] = g_remainR[b * MM + idx];
        smcr[idx] = g_ccrr[b * MM + idx];
    }
    __syncthreads();

    // this warp's rows + previous-iteration scale
    float x1[RPW], y1[RPW], z1[RPW], srow[RPW], rdp[RPW], scaleP[RPW];
    bool hasPrev = false;
#pragma unroll
    for (int r = 0; r < RPW; r++) {
        const float* p1 = xyz1 + ((size_t)b * NN + row0 + r) * 3;
        x1[r] = p1[0]; y1[r] = p1[1]; z1[r] = p1[2];
        srow[r] = 0.f; rdp[r] = 0.f;
        scaleP[r] = g_scaleP[b * NN + row0 + r];
        if (scaleP[r] != 0.f) hasPrev = true;
    }

    // ---- loop 1: new-level row sums + old-level deferred decrement ----------
    float racc = 0.f;                        // ZERO mode: sum(rr) shared by all rows
    for (int c = 0; c < MM; c += 32) {
        const int col = c + lane;
        const float bx = smx[col], by = smy[col], bz = smz[col];
        float dd[RPW];
        float mn = 3.0e38f;
#pragma unroll
        for (int r = 0; r < RPW; r++) {
            float dx = x1[r] - bx, dy = y1[r] - by, dz = z1[r] - bz;
            dd[r] = fmaf(dz, dz, fmaf(dy, dy, dx * dx));
            mn = fminf(mn, dd[r]);
        }

        if (MODE == MODE_ZERO) {
            racc += smrr[col];
        } else {
            bool activeN = true;
            if (MODE == MODE_SKIP) activeN = __any_sync(0xffffffffu, mn < thrN);
            if (activeN) {
                const float lrr = smrr[col];
#pragma unroll
                for (int r = 0; r < RPW; r++)
                    srow[r] = fmaf(ex2f(l2new * dd[r]), lrr, srow[r]);
            }
        }

        if (hasPrev && __any_sync(0xffffffffu, mn < thrO)) {
            const float lcr = smcr[col];
#pragma unroll
            for (int r = 0; r < RPW; r++)
                rdp[r] = fmaf(ex2f(l2old * dd[r]), lcr, rdp[r]);
        }
    }
    if (MODE == MODE_ZERO) {
#pragma unroll
        for (int r = 0; r < RPW; r++) srow[r] = racc;
    }

    // ---- warp-only reduction (butterfly -> all lanes hold the sums) ---------
#pragma unroll
    for (int off = 16; off > 0; off >>= 1) {
#pragma unroll
        for (int r = 0; r < RPW; r++) {
            srow[r] += __shfl_xor_sync(0xffffffffu, srow[r], off);
            rdp[r]  += __shfl_xor_sync(0xffffffffu, rdp[r],  off);
        }
    }

    float scale[RPW];
    unsigned actmask = 0;
#pragma unroll
    for (int r = 0; r < RPW; r++) {
        const int li = b * NN + row0 + r;
        float rl = fmaxf(g_remainL[li] - scaleP[r] * rdp[r], 0.f);
        scale[r] = rl / (srow[r] + EPSv);
        if (srow[r] != 0.f) actmask |= (1u << r);
        if (lane == 0) {
            g_remainL[li] = rl;
            g_scaleP[li] = (srow[r] != 0.f) ? scale[r] : 0.f;
        }
    }

    if (!actmask) return;   // whole warp: nothing to accumulate

    // ---- loop 2: recompute e (bit-identical), scale, column partials --------
    for (int c = 0; c < MM; c += 32) {
        const int col = c + lane;
        const float bx = smx[col], by = smy[col], bz = smz[col];
        const float lrr = smrr[col];
        float csum = 0.f, ccost = 0.f;
#pragma unroll
        for (int r = 0; r < RPW; r++) {
            if (actmask & (1u << r)) {
                float dx = x1[r] - bx, dy = y1[r] - by, dz = z1[r] - bz;
                float dd = fmaf(dz, dz, fmaf(dy, dy, dx * dx));
                float e = (MODE == MODE_ZERO) ? lrr : ex2f(l2new * dd) * lrr;
                float wv = e * scale[r];
                csum += wv;
                ccost = fmaf(wv, sqrt_approx(dd), ccost);
            }
        }
        atomicAdd(&g_sumr[b * MM + col], csum);
        atomicAdd(&g_colcost[b * MM + col], ccost);
    }
}

// Column saturation + remainR update + cost accumulation; stores ccrr =
// cons * remainR_prev for the next iteration's deferred remainL decrement.
__global__ void __launch_bounds__(256) cons_kernel(float* __restrict__ out) {
    const int b = blockIdx.y;
    const int l = blockIdx.x * 256 + threadIdx.x;
    const int idx = b * MM + l;

    float sr  = g_sumr[idx];
    float rrv = g_remainR[idx];
    float c = fminf(rrv / (sr + EPSv), 1.0f);
    g_ccrr[idx] = c * rrv;
    g_remainR[idx] = fmaxf(rrv - sr * c, 0.f);
    float local = c * g_colcost[idx];
    g_sumr[idx] = 0.f;
    g_colcost[idx] = 0.f;

#pragma unroll
    for (int off = 16; off > 0; off >>= 1)
        local += __shfl_xor_sync(0xffffffffu, local, off);

    __shared__ float red[8];
    const int warp = threadIdx.x >> 5, lane = threadIdx.x & 31;
    if (lane == 0) red[warp] = local;
    __syncthreads();
    if (threadIdx.x == 0) {
        float s = 0.f;
#pragma unroll
        for (int w = 0; w < 8; w++) s += red[w];
        atomicAdd(&out[b], s);
    }
}

// ---------------------------------------------------------------------------
extern "C" void kernel_launch(void* const* d_in, const int* in_sizes, int n_in,
                              void* d_out, int out_size) {
    (void)in_sizes; (void)n_in; (void)out_size;
    const float* xyz1 = (const float*)d_in[0];
    const float* xyz2 = (const float*)d_in[1];
    float* out = (float*)d_out;

    const float mx = (float)(NN > MM ? NN : MM);
    init_kernel<<<(BB * MM + 255) / 256, 256>>>(out, mx / (float)NN, mx / (float)MM);

    const float LOG2E = 1.4426950408889634f;
    dim3 grid(NN / ROWS_PB, BB);     // (64, 16) = 1024 blocks
    dim3 cgrid(MM / 256, BB);        // (8, 16) = 128 blocks

    float l2old = 0.f, thrO = 3.0e38f;
    for (int j = 7; j >= -2; --j) {
        float level = (j == -2) ? 0.f : -powf(4.f, (float)j);
        float l2new = level * LOG2E;
        float thrN = (level == 0.f) ? 3.0e38f : (-126.0f / l2new);

        if (j == -2) {
            passA_kernel<MODE_ZERO><<<grid, 256>>>(xyz1, xyz2, 0.f, l2old, thrN, thrO);
        } else if (level < -200.f) {
            passA_kernel<MODE_SKIP><<<grid, 256>>>(xyz1, xyz2, l2new, l2old, thrN, thrO);
        } else {
            passA_kernel<MODE_NORM><<<grid, 256>>>(xyz1, xyz2, l2new, l2old, thrN, thrO);
        }
        cons_kernel<<<cgrid, 256>>>(out);

        l2old = l2new;
        thrO = thrN;
    }
}

// round 10
// speedup vs baseline: 6.4853x; 1.2832x over previous
#include <cuda_runtime.h>
#include <math.h>

// Problem shape (fixed by the dataset): xyz1 (16,2048,3), xyz2 (16,2048,3)
#define BB 16
#define NN 2048
#define MM 2048
#define RPW 4                 // rows per warp (2 f32x2 pairs)
#define WPB 8                 // warps per block (256 threads)
#define ROWS_PB (RPW * WPB)   // 32 rows per block

constexpr float EPSv = 1e-9f;

// -------- device scratch (vectors only; NO matrix scratch) ------------------
__device__ float g_remainL[BB * NN];
__device__ float g_scaleP[BB * NN];   // scale_i of previous iteration (0 if row sum was 0)
__device__ float g_remainR[BB * MM];
__device__ float g_ccrr[BB * MM];     // cons * remainR_prev of previous iteration
__device__ float g_sumr[BB * MM];     // column sums of w'
__device__ float g_colcost[BB * MM];  // column sums of w'*sqrt(d2)

typedef unsigned long long u64;

__device__ __forceinline__ float ex2f(float x) {
    float y; asm("ex2.approx.ftz.f32 %0, %1;" : "=f"(y) : "f"(x)); return y;
}
__device__ __forceinline__ float sqrt_approx(float x) {
    float y; asm("sqrt.approx.ftz.f32 %0, %1;" : "=f"(y) : "f"(x)); return y;
}
__device__ __forceinline__ u64 pack2(float lo, float hi) {
    u64 r;
    asm("mov.b64 %0, {%1, %2};" : "=l"(r)
        : "r"(__float_as_uint(lo)), "r"(__float_as_uint(hi)));
    return r;
}
__device__ __forceinline__ void unpack2(u64 v, float& lo, float& hi) {
    unsigned a, b;
    asm("mov.b64 {%0, %1}, %2;" : "=r"(a), "=r"(b) : "l"(v));
    lo = __uint_as_float(a); hi = __uint_as_float(b);
}
__device__ __forceinline__ u64 add2(u64 a, u64 b) {
    u64 r; asm("add.rn.f32x2 %0, %1, %2;" : "=l"(r) : "l"(a), "l"(b)); return r;
}
__device__ __forceinline__ u64 mul2(u64 a, u64 b) {
    u64 r; asm("mul.rn.f32x2 %0, %1, %2;" : "=l"(r) : "l"(a), "l"(b)); return r;
}
__device__ __forceinline__ u64 fma2(u64 a, u64 b, u64 c) {
    u64 r; asm("fma.rn.f32x2 %0, %1, %2, %3;" : "=l"(r) : "l"(a), "l"(b), "l"(c)); return r;
}

// ---------------------------------------------------------------------------
__global__ void init_kernel(float* __restrict__ out, float initL, float initR) {
    int idx = blockIdx.x * blockDim.x + threadIdx.x;
    if (idx < BB * NN) { g_remainL[idx] = initL; g_scaleP[idx] = 0.f; }
    if (idx < BB * MM) { g_remainR[idx] = initR; g_ccrr[idx] = 0.f;
                         g_sumr[idx] = 0.f; g_colcost[idx] = 0.f; }
    if (idx < BB) out[idx] = 0.f;
}

#define MODE_NORM 0
#define MODE_SKIP 1
#define MODE_ZERO 2

// One annealing iteration, warp-autonomous, zero matrix traffic.
// d2 computed with packed f32x2 math (rows in pairs); underflow votes use the
// exp arguments directly (dd < thr  <=>  l2*dd > -126). Loop2 recomputes e
// bit-identically (same packed ops + FTZ exact-zero underflow).
template <int MODE>
__global__ void __launch_bounds__(256, 4) passA_kernel(
    const float* __restrict__ xyz1, const float* __restrict__ xyz2,
    float l2new, float l2old)
{
    __shared__ float4 sm_pt4[MM];    // {x, y, z, remainR}
    __shared__ float  sm_cr[MM];     // ccrr

    const int b = blockIdx.y;
    const int t = threadIdx.x, warp = t >> 5, lane = t & 31;
    const int row0 = blockIdx.x * ROWS_PB + warp * RPW;

    // stage column data (one barrier total)
    for (int idx = t; idx < MM; idx += 256) {
        const float* p2 = xyz2 + ((size_t)b * MM + idx) * 3;
        sm_pt4[idx] = make_float4(p2[0], p2[1], p2[2], g_remainR[b * MM + idx]);
        sm_cr[idx] = g_ccrr[b * MM + idx];
    }
    __syncthreads();

    // this warp's rows: packed negated coordinates (pairs (0,1) and (2,3))
    float scaleP[RPW], srow[RPW], rdp[RPW];
    float xs[RPW], ys[RPW], zs[RPW];
    bool hasPrev = false;
#pragma unroll
    for (int r = 0; r < RPW; r++) {
        const float* p1 = xyz1 + ((size_t)b * NN + row0 + r) * 3;
        xs[r] = -p1[0]; ys[r] = -p1[1]; zs[r] = -p1[2];
        srow[r] = 0.f; rdp[r] = 0.f;
        scaleP[r] = g_scaleP[b * NN + row0 + r];
        if (scaleP[r] != 0.f) hasPrev = true;
    }
    const u64 nx01 = pack2(xs[0], xs[1]), nx23 = pack2(xs[2], xs[3]);
    const u64 ny01 = pack2(ys[0], ys[1]), ny23 = pack2(ys[2], ys[3]);
    const u64 nz01 = pack2(zs[0], zs[1]), nz23 = pack2(zs[2], zs[3]);
    const u64 l2n2 = pack2(l2new, l2new);
    const u64 l2o2 = pack2(l2old, l2old);

    // ---- loop 1: new-level row sums + old-level deferred decrement ----------
    float racc = 0.f;                      // ZERO mode: sum(rr) shared by all rows
    for (int c = 0; c < MM; c += 32) {
        const int col = c + lane;
        const float4 pt = sm_pt4[col];
        const u64 bx2 = pack2(pt.x, pt.x);
        const u64 by2 = pack2(pt.y, pt.y);
        const u64 bz2 = pack2(pt.z, pt.z);

        u64 dd01, dd23;
        {
            u64 dx = add2(bx2, nx01), dy = add2(by2, ny01), dz = add2(bz2, nz01);
            dd01 = fma2(dz, dz, fma2(dy, dy, mul2(dx, dx)));
            dx = add2(bx2, nx23); dy = add2(by2, ny23); dz = add2(bz2, nz23);
            dd23 = fma2(dz, dz, fma2(dy, dy, mul2(dx, dx)));
        }

        if (MODE == MODE_ZERO) {
            racc += pt.w;
        } else {
            float a0, a1, a2, a3;
            unpack2(mul2(dd01, l2n2), a0, a1);
            unpack2(mul2(dd23, l2n2), a2, a3);
            bool act = true;
            if (MODE == MODE_SKIP) {
                float amax = fmaxf(fmaxf(a0, a1), fmaxf(a2, a3));
                act = __any_sync(0xffffffffu, amax > -126.f);
            }
            if (act) {
                const float lrr = pt.w;
                srow[0] = fmaf(ex2f(a0), lrr, srow[0]);
                srow[1] = fmaf(ex2f(a1), lrr, srow[1]);
                srow[2] = fmaf(ex2f(a2), lrr, srow[2]);
                srow[3] = fmaf(ex2f(a3), lrr, srow[3]);
            }
        }

        if (hasPrev) {
            float b0, b1, b2, b3;
            unpack2(mul2(dd01, l2o2), b0, b1);
            unpack2(mul2(dd23, l2o2), b2, b3);
            float bmax = fmaxf(fmaxf(b0, b1), fmaxf(b2, b3));
            if (__any_sync(0xffffffffu, bmax > -126.f)) {
                const float lcr = sm_cr[col];
                rdp[0] = fmaf(ex2f(b0), lcr, rdp[0]);
                rdp[1] = fmaf(ex2f(b1), lcr, rdp[1]);
                rdp[2] = fmaf(ex2f(b2), lcr, rdp[2]);
                rdp[3] = fmaf(ex2f(b3), lcr, rdp[3]);
            }
        }
    }
    if (MODE == MODE_ZERO) {
#pragma unroll
        for (int r = 0; r < RPW; r++) srow[r] = racc;
    }

    // ---- warp-only reduction (butterfly -> all lanes hold the sums) ---------
#pragma unroll
    for (int off = 16; off > 0; off >>= 1) {
#pragma unroll
        for (int r = 0; r < RPW; r++) {
            srow[r] += __shfl_xor_sync(0xffffffffu, srow[r], off);
            rdp[r]  += __shfl_xor_sync(0xffffffffu, rdp[r],  off);
        }
    }

    float scale[RPW];
    unsigned actmask = 0;
#pragma unroll
    for (int r = 0; r < RPW; r++) {
        const int li = b * NN + row0 + r;
        float rl = fmaxf(g_remainL[li] - scaleP[r] * rdp[r], 0.f);
        scale[r] = rl / (srow[r] + EPSv);
        if (srow[r] != 0.f) actmask |= (1u << r);
        if (lane == 0) {
            g_remainL[li] = rl;
            g_scaleP[li] = (srow[r] != 0.f) ? scale[r] : 0.f;
        }
    }

    if (!actmask) return;   // whole warp: nothing to accumulate

    // ---- loop 2: recompute e (bit-identical), scale, column partials --------
    for (int c = 0; c < MM; c += 32) {
        const int col = c + lane;
        const float4 pt = sm_pt4[col];
        const u64 bx2 = pack2(pt.x, pt.x);
        const u64 by2 = pack2(pt.y, pt.y);
        const u64 bz2 = pack2(pt.z, pt.z);

        u64 dd01, dd23;
        {
            u64 dx = add2(bx2, nx01), dy = add2(by2, ny01), dz = add2(bz2, nz01);
            dd01 = fma2(dz, dz, fma2(dy, dy, mul2(dx, dx)));
            dx = add2(bx2, nx23); dy = add2(by2, ny23); dz = add2(bz2, nz23);
            dd23 = fma2(dz, dz, fma2(dy, dy, mul2(dx, dx)));
        }

        float a0 = 0.f, a1 = 0.f, a2 = 0.f, a3 = 0.f;
        if (MODE != MODE_ZERO) {
            unpack2(mul2(dd01, l2n2), a0, a1);
            unpack2(mul2(dd23, l2n2), a2, a3);
            if (MODE == MODE_SKIP) {
                float amax = fmaxf(fmaxf(a0, a1), fmaxf(a2, a3));
                if (!__any_sync(0xffffffffu, amax > -126.f)) continue;   // all e == 0
            }
        }
        float d0, d1, d2v, d3;
        unpack2(dd01, d0, d1);
        unpack2(dd23, d2v, d3);

        const float lrr = pt.w;
        float csum = 0.f, ccost = 0.f;
        {
            float av[RPW] = {a0, a1, a2, a3};
            float dv[RPW] = {d0, d1, d2v, d3};
#pragma unroll
            for (int r = 0; r < RPW; r++) {
                if (actmask & (1u << r)) {
                    float e = (MODE == MODE_ZERO) ? lrr : ex2f(av[r]) * lrr;
                    float wv = e * scale[r];
                    csum += wv;
                    ccost = fmaf(wv, sqrt_approx(dv[r]), ccost);
                }
            }
        }
        atomicAdd(&g_sumr[b * MM + col], csum);
        atomicAdd(&g_colcost[b * MM + col], ccost);
    }
}

// Column saturation + remainR update + cost accumulation; stores ccrr =
// cons * remainR_prev for the next iteration's deferred remainL decrement.
__global__ void __launch_bounds__(256) cons_kernel(float* __restrict__ out) {
    const int b = blockIdx.y;
    const int l = blockIdx.x * 256 + threadIdx.x;
    const int idx = b * MM + l;

    float sr  = g_sumr[idx];
    float rrv = g_remainR[idx];
    float c = fminf(rrv / (sr + EPSv), 1.0f);
    g_ccrr[idx] = c * rrv;
    g_remainR[idx] = fmaxf(rrv - sr * c, 0.f);
    float local = c * g_colcost[idx];
    g_sumr[idx] = 0.f;
    g_colcost[idx] = 0.f;

#pragma unroll
    for (int off = 16; off > 0; off >>= 1)
        local += __shfl_xor_sync(0xffffffffu, local, off);

    __shared__ float red[8];
    const int warp = threadIdx.x >> 5, lane = threadIdx.x & 31;
    if (lane == 0) red[warp] = local;
    __syncthreads();
    if (threadIdx.x == 0) {
        float s = 0.f;
#pragma unroll
        for (int w = 0; w < 8; w++) s += red[w];
        atomicAdd(&out[b], s);
    }
}

// ---------------------------------------------------------------------------
extern "C" void kernel_launch(void* const* d_in, const int* in_sizes, int n_in,
                              void* d_out, int out_size) {
    (void)in_sizes; (void)n_in; (void)out_size;
    const float* xyz1 = (const float*)d_in[0];
    const float* xyz2 = (const float*)d_in[1];
    float* out = (float*)d_out;

    const float mx = (float)(NN > MM ? NN : MM);
    init_kernel<<<(BB * MM + 255) / 256, 256>>>(out, mx / (float)NN, mx / (float)MM);

    const float LOG2E = 1.4426950408889634f;
    dim3 grid(NN / ROWS_PB, BB);     // (64, 16) = 1024 blocks
    dim3 cgrid(MM / 256, BB);        // (8, 16) = 128 blocks

    float l2old = 0.f;
    for (int j = 7; j >= -2; --j) {
        float level = (j == -2) ? 0.f : -powf(4.f, (float)j);
        float l2new = level * LOG2E;

        if (j == -2) {
            passA_kernel<MODE_ZERO><<<grid, 256>>>(xyz1, xyz2, 0.f, l2old);
        } else if (level < -200.f) {
            passA_kernel<MODE_SKIP><<<grid, 256>>>(xyz1, xyz2, l2new, l2old);
        } else {
            passA_kernel<MODE_NORM><<<grid, 256>>>(xyz1, xyz2, l2new, l2old);
        }
        cons_kernel<<<cgrid, 256>>>(out);

        l2old = l2new;
    }
}

// round 11
// speedup vs baseline: 6.8413x; 1.0549x over previous
#include <cuda_runtime.h>
#include <math.h>

// Problem shape (fixed by the dataset): xyz1 (16,2048,3), xyz2 (16,2048,3)
#define BB 16
#define NN 2048
#define MM 2048
#define RPW 4                 // rows per warp (2 f32x2 pairs)
#define WPB 8                 // warps per block (256 threads)
#define ROWS_PB (RPW * WPB)   // 32 rows per block

constexpr float EPSv = 1e-9f;

// -------- device scratch (vectors only; NO matrix scratch) ------------------
__device__ float  g_remainL[BB * NN];
__device__ float  g_scaleP[BB * NN];   // scale_i of previous iteration (0 if row sum was 0)
__device__ float  g_remainR[BB * MM];
__device__ float  g_ccrr[BB * MM];     // cons * remainR_prev of previous iteration
__device__ float2 g_colacc[BB * MM];   // .x = column sum of w', .y = column sum of w'*sqrt(d2)

typedef unsigned long long u64;

__device__ __forceinline__ float ex2f(float x) {
    float y; asm("ex2.approx.ftz.f32 %0, %1;" : "=f"(y) : "f"(x)); return y;
}
__device__ __forceinline__ float sqrt_approx(float x) {
    float y; asm("sqrt.approx.ftz.f32 %0, %1;" : "=f"(y) : "f"(x)); return y;
}
__device__ __forceinline__ u64 pack2(float lo, float hi) {
    u64 r;
    asm("mov.b64 %0, {%1, %2};" : "=l"(r)
        : "r"(__float_as_uint(lo)), "r"(__float_as_uint(hi)));
    return r;
}
__device__ __forceinline__ void unpack2(u64 v, float& lo, float& hi) {
    unsigned a, b;
    asm("mov.b64 {%0, %1}, %2;" : "=r"(a), "=r"(b) : "l"(v));
    lo = __uint_as_float(a); hi = __uint_as_float(b);
}
__device__ __forceinline__ u64 add2(u64 a, u64 b) {
    u64 r; asm("add.rn.f32x2 %0, %1, %2;" : "=l"(r) : "l"(a), "l"(b)); return r;
}
__device__ __forceinline__ u64 mul2(u64 a, u64 b) {
    u64 r; asm("mul.rn.f32x2 %0, %1, %2;" : "=l"(r) : "l"(a), "l"(b)); return r;
}
__device__ __forceinline__ u64 fma2(u64 a, u64 b, u64 c) {
    u64 r; asm("fma.rn.f32x2 %0, %1, %2, %3;" : "=l"(r) : "l"(a), "l"(b), "l"(c)); return r;
}
__device__ __forceinline__ void red_add_v2(float2* p, float a, float b) {
    asm volatile("red.global.add.v2.f32 [%0], {%1, %2};"
                 :: "l"(p), "f"(a), "f"(b) : "memory");
}

// ---------------------------------------------------------------------------
__global__ void init_kernel(float* __restrict__ out, float initL, float initR) {
    int idx = blockIdx.x * blockDim.x + threadIdx.x;
    if (idx < BB * NN) { g_remainL[idx] = initL; g_scaleP[idx] = 0.f; }
    if (idx < BB * MM) { g_remainR[idx] = initR; g_ccrr[idx] = 0.f;
                         g_colacc[idx] = make_float2(0.f, 0.f); }
    if (idx < BB) out[idx] = 0.f;
}

#define MODE_NORM 0
#define MODE_SKIP 1
#define MODE_ZERO 2

// One annealing iteration, warp-autonomous, zero matrix traffic.
// d2 with packed f32x2 math; exp(l2old*dd) recovered as e_new^4 (the schedule
// guarantees l2old == 4*l2new for all non-ZERO transitions; FTZ underflow
// boundaries coincide, so vote-skipped chunks contribute exactly 0 to both).
template <int MODE>
__global__ void __launch_bounds__(256, 4) passA_kernel(
    const float* __restrict__ xyz1, const float* __restrict__ xyz2,
    float l2new, float l2old)
{
    __shared__ float4 sm_pt4[MM];    // {x, y, z, remainR}
    __shared__ float  sm_cr[MM];     // ccrr

    const int b = blockIdx.y;
    const int t = threadIdx.x, warp = t >> 5, lane = t & 31;
    const int row0 = blockIdx.x * ROWS_PB + warp * RPW;

    // stage column data (one barrier total)
    for (int idx = t; idx < MM; idx += 256) {
        const float* p2 = xyz2 + ((size_t)b * MM + idx) * 3;
        sm_pt4[idx] = make_float4(p2[0], p2[1], p2[2], g_remainR[b * MM + idx]);
        sm_cr[idx] = g_ccrr[b * MM + idx];
    }
    __syncthreads();

    // this warp's rows: packed negated coordinates (pairs (0,1) and (2,3))
    float scaleP[RPW], srow[RPW], rdp[RPW];
    float xs[RPW], ys[RPW], zs[RPW];
    bool hasPrev = false;
#pragma unroll
    for (int r = 0; r < RPW; r++) {
        const float* p1 = xyz1 + ((size_t)b * NN + row0 + r) * 3;
        xs[r] = -p1[0]; ys[r] = -p1[1]; zs[r] = -p1[2];
        srow[r] = 0.f; rdp[r] = 0.f;
        scaleP[r] = g_scaleP[b * NN + row0 + r];
        if (scaleP[r] != 0.f) hasPrev = true;
    }
    const u64 nx01 = pack2(xs[0], xs[1]), nx23 = pack2(xs[2], xs[3]);
    const u64 ny01 = pack2(ys[0], ys[1]), ny23 = pack2(ys[2], ys[3]);
    const u64 nz01 = pack2(zs[0], zs[1]), nz23 = pack2(zs[2], zs[3]);
    const u64 l2n2 = pack2(l2new, l2new);
    const u64 l2o2 = pack2(l2old, l2old);

    // ---- loop 1: new-level row sums + old-level deferred decrement ----------
    float racc = 0.f;                      // ZERO mode: sum(rr) shared by all rows
    for (int c = 0; c < MM; c += 32) {
        const int col = c + lane;
        const float4 pt = sm_pt4[col];
        const u64 bx2 = pack2(pt.x, pt.x);
        const u64 by2 = pack2(pt.y, pt.y);
        const u64 bz2 = pack2(pt.z, pt.z);

        u64 dd01, dd23;
        {
            u64 dx = add2(bx2, nx01), dy = add2(by2, ny01), dz = add2(bz2, nz01);
            dd01 = fma2(dz, dz, fma2(dy, dy, mul2(dx, dx)));
            dx = add2(bx2, nx23); dy = add2(by2, ny23); dz = add2(bz2, nz23);
            dd23 = fma2(dz, dz, fma2(dy, dy, mul2(dx, dx)));
        }

        if (MODE == MODE_ZERO) {
            racc += pt.w;
            // old level computed directly (e_new == 1 here, ^4 trick unusable)
            if (hasPrev) {
                float b0, b1, b2, b3;
                unpack2(mul2(dd01, l2o2), b0, b1);
                unpack2(mul2(dd23, l2o2), b2, b3);
                const float lcr = sm_cr[col];
                rdp[0] = fmaf(ex2f(b0), lcr, rdp[0]);
                rdp[1] = fmaf(ex2f(b1), lcr, rdp[1]);
                rdp[2] = fmaf(ex2f(b2), lcr, rdp[2]);
                rdp[3] = fmaf(ex2f(b3), lcr, rdp[3]);
            }
        } else {
            float a0, a1, a2, a3;
            unpack2(mul2(dd01, l2n2), a0, a1);
            unpack2(mul2(dd23, l2n2), a2, a3);
            bool act = true;
            if (MODE == MODE_SKIP) {
                float amax = fmaxf(fmaxf(a0, a1), fmaxf(a2, a3));
                act = __any_sync(0xffffffffu, amax > -126.f);
            }
            if (act) {
                const float lrr = pt.w;
                float e0 = ex2f(a0), e1 = ex2f(a1), e2 = ex2f(a2), e3 = ex2f(a3);
                srow[0] = fmaf(e0, lrr, srow[0]);
                srow[1] = fmaf(e1, lrr, srow[1]);
                srow[2] = fmaf(e2, lrr, srow[2]);
                srow[3] = fmaf(e3, lrr, srow[3]);
                if (hasPrev) {
                    const float lcr = sm_cr[col];
                    float q0 = e0 * e0, q1 = e1 * e1, q2 = e2 * e2, q3 = e3 * e3;
                    rdp[0] = fmaf(q0 * q0, lcr, rdp[0]);
                    rdp[1] = fmaf(q1 * q1, lcr, rdp[1]);
                    rdp[2] = fmaf(q2 * q2, lcr, rdp[2]);
                    rdp[3] = fmaf(q3 * q3, lcr, rdp[3]);
                }
            }
        }
    }
    if (MODE == MODE_ZERO) {
#pragma unroll
        for (int r = 0; r < RPW; r++) srow[r] = racc;
    }

    // ---- warp-only reduction (butterfly -> all lanes hold the sums) ---------
#pragma unroll
    for (int off = 16; off > 0; off >>= 1) {
#pragma unroll
        for (int r = 0; r < RPW; r++) {
            srow[r] += __shfl_xor_sync(0xffffffffu, srow[r], off);
            rdp[r]  += __shfl_xor_sync(0xffffffffu, rdp[r],  off);
        }
    }

    float scale[RPW];
    unsigned actmask = 0;
#pragma unroll
    for (int r = 0; r < RPW; r++) {
        const int li = b * NN + row0 + r;
        float rl = fmaxf(g_remainL[li] - scaleP[r] * rdp[r], 0.f);
        scale[r] = rl / (srow[r] + EPSv);
        if (srow[r] != 0.f) actmask |= (1u << r);
        if (lane == 0) {
            g_remainL[li] = rl;
            g_scaleP[li] = (srow[r] != 0.f) ? scale[r] : 0.f;
        }
    }

    if (!actmask) return;   // whole warp: nothing to accumulate

    // ---- loop 2: recompute e (bit-identical), scale, column partials --------
    for (int c = 0; c < MM; c += 32) {
        const int col = c + lane;
        const float4 pt = sm_pt4[col];
        const u64 bx2 = pack2(pt.x, pt.x);
        const u64 by2 = pack2(pt.y, pt.y);
        const u64 bz2 = pack2(pt.z, pt.z);

        u64 dd01, dd23;
        {
            u64 dx = add2(bx2, nx01), dy = add2(by2, ny01), dz = add2(bz2, nz01);
            dd01 = fma2(dz, dz, fma2(dy, dy, mul2(dx, dx)));
            dx = add2(bx2, nx23); dy = add2(by2, ny23); dz = add2(bz2, nz23);
            dd23 = fma2(dz, dz, fma2(dy, dy, mul2(dx, dx)));
        }

        float a0 = 0.f, a1 = 0.f, a2 = 0.f, a3 = 0.f;
        if (MODE != MODE_ZERO) {
            unpack2(mul2(dd01, l2n2), a0, a1);
            unpack2(mul2(dd23, l2n2), a2, a3);
            if (MODE == MODE_SKIP) {
                float amax = fmaxf(fmaxf(a0, a1), fmaxf(a2, a3));
                if (!__any_sync(0xffffffffu, amax > -126.f)) continue;   // all e == 0
            }
        }
        float d0, d1, d2v, d3;
        unpack2(dd01, d0, d1);
        unpack2(dd23, d2v, d3);

        const float lrr = pt.w;
        float csum = 0.f, ccost = 0.f;
        {
            float av[RPW] = {a0, a1, a2, a3};
            float dv[RPW] = {d0, d1, d2v, d3};
#pragma unroll
            for (int r = 0; r < RPW; r++) {
                if (actmask & (1u << r)) {
                    float e = (MODE == MODE_ZERO) ? lrr : ex2f(av[r]) * lrr;
                    float wv = e * scale[r];
                    csum += wv;
                    ccost = fmaf(wv, sqrt_approx(dv[r]), ccost);
                }
            }
        }
        red_add_v2(&g_colacc[b * MM + col], csum, ccost);
    }
}

// Column saturation + remainR update + cost accumulation; stores ccrr =
// cons * remainR_prev for the next iteration's deferred remainL decrement.
__global__ void __launch_bounds__(256) cons_kernel(float* __restrict__ out) {
    const int b = blockIdx.y;
    const int l = blockIdx.x * 256 + threadIdx.x;
    const int idx = b * MM + l;

    float2 acc = g_colacc[idx];
    float sr  = acc.x;
    float rrv = g_remainR[idx];
    float c = fminf(rrv / (sr + EPSv), 1.0f);
    g_ccrr[idx] = c * rrv;
    g_remainR[idx] = fmaxf(rrv - sr * c, 0.f);
    float local = c * acc.y;
    g_colacc[idx] = make_float2(0.f, 0.f);

#pragma unroll
    for (int off = 16; off > 0; off >>= 1)
        local += __shfl_xor_sync(0xffffffffu, local, off);

    __shared__ float red[8];
    const int warp = threadIdx.x >> 5, lane = threadIdx.x & 31;
    if (lane == 0) red[warp] = local;
    __syncthreads();
    if (threadIdx.x == 0) {
        float s = 0.f;
#pragma unroll
        for (int w = 0; w < 8; w++) s += red[w];
        atomicAdd(&out[b], s);
    }
}

// ---------------------------------------------------------------------------
extern "C" void kernel_launch(void* const* d_in, const int* in_sizes, int n_in,
                              void* d_out, int out_size) {
    (void)in_sizes; (void)n_in; (void)out_size;
    const float* xyz1 = (const float*)d_in[0];
    const float* xyz2 = (const float*)d_in[1];
    float* out = (float*)d_out;

    const float mx = (float)(NN > MM ? NN : MM);
    init_kernel<<<(BB * MM + 255) / 256, 256>>>(out, mx / (float)NN, mx / (float)MM);

    const float LOG2E = 1.4426950408889634f;
    dim3 grid(NN / ROWS_PB, BB);     // (64, 16) = 1024 blocks
    dim3 cgrid(MM / 256, BB);        // (8, 16) = 128 blocks

    float l2old = 0.f;
    for (int j = 7; j >= -2; --j) {
        float level = (j == -2) ? 0.f : -powf(4.f, (float)j);
        float l2new = level * LOG2E;

        if (j == -2) {
            passA_kernel<MODE_ZERO><<<grid, 256>>>(xyz1, xyz2, 0.f, l2old);
        } else if (level < -200.f) {
            passA_kernel<MODE_SKIP><<<grid, 256>>>(xyz1, xyz2, l2new, l2old);
        } else {
            passA_kernel<MODE_NORM><<<grid, 256>>>(xyz1, xyz2, l2new, l2old);
        }
        cons_kernel<<<cgrid, 256>>>(out);

        l2old = l2new;
    }
}

// round 12
// speedup vs baseline: 6.8908x; 1.0072x over previous
#include <cuda_runtime.h>
#include <math.h>

// Problem shape (fixed by the dataset): xyz1 (16,2048,3), xyz2 (16,2048,3)
#define BB 16
#define NN 2048
#define MM 2048
#define RPW 4                 // rows per warp (2 f32x2 pairs)
#define WPB 8                 // warps per block (256 threads)
#define ROWS_PB (RPW * WPB)   // 32 rows per block

constexpr float EPSv = 1e-9f;

// -------- device scratch (vectors only; NO matrix scratch) ------------------
__device__ float  g_remainL[BB * NN];
__device__ float  g_scaleP[BB * NN];   // scale_i of previous iteration (0 if row sum was 0)
__device__ float  g_remainR[BB * MM];
__device__ float  g_ccrr[BB * MM];     // cons * remainR_prev of previous iteration
__device__ float2 g_colacc[BB * MM];   // .x = col sum of w', .y = col sum of w'*sqrt(d2)

typedef unsigned long long u64;

__device__ __forceinline__ float ex2f(float x) {
    float y; asm("ex2.approx.ftz.f32 %0, %1;" : "=f"(y) : "f"(x)); return y;
}
__device__ __forceinline__ float sqrt_approx(float x) {
    float y; asm("sqrt.approx.ftz.f32 %0, %1;" : "=f"(y) : "f"(x)); return y;
}
__device__ __forceinline__ u64 pack2(float lo, float hi) {
    u64 r;
    asm("mov.b64 %0, {%1, %2};" : "=l"(r)
        : "r"(__float_as_uint(lo)), "r"(__float_as_uint(hi)));
    return r;
}
__device__ __forceinline__ void unpack2(u64 v, float& lo, float& hi) {
    unsigned a, b;
    asm("mov.b64 {%0, %1}, %2;" : "=r"(a), "=r"(b) : "l"(v));
    lo = __uint_as_float(a); hi = __uint_as_float(b);
}
__device__ __forceinline__ u64 add2(u64 a, u64 b) {
    u64 r; asm("add.rn.f32x2 %0, %1, %2;" : "=l"(r) : "l"(a), "l"(b)); return r;
}
__device__ __forceinline__ u64 mul2(u64 a, u64 b) {
    u64 r; asm("mul.rn.f32x2 %0, %1, %2;" : "=l"(r) : "l"(a), "l"(b)); return r;
}
__device__ __forceinline__ u64 fma2(u64 a, u64 b, u64 c) {
    u64 r; asm("fma.rn.f32x2 %0, %1, %2, %3;" : "=l"(r) : "l"(a), "l"(b), "l"(c)); return r;
}
__device__ __forceinline__ void red_add_v2(float2* p, float a, float b) {
    asm volatile("red.global.add.v2.f32 [%0], {%1, %2};"
                 :: "l"(p), "f"(a), "f"(b) : "memory");
}

// ---------------------------------------------------------------------------
__global__ void init_kernel(float* __restrict__ out, float initL, float initR) {
    int idx = blockIdx.x * blockDim.x + threadIdx.x;
    if (idx < BB * NN) { g_remainL[idx] = initL; g_scaleP[idx] = 0.f; }
    if (idx < BB * MM) { g_remainR[idx] = initR; g_ccrr[idx] = 0.f;
                         g_colacc[idx] = make_float2(0.f, 0.f); }
    if (idx < BB) out[idx] = 0.f;
}

#define MODE_NORM 0
#define MODE_SKIP 1
#define MODE_ZERO 2

// One annealing iteration, warp-autonomous, zero matrix traffic.
// f32x2 packed math throughout; old-level exp recovered as e_new^4 (schedule
// guarantees l2old == 4*l2new for non-ZERO transitions, FTZ boundaries
// coincide). SKIP mode: loop1's per-chunk ballot outcome is memoized in a
// 64-bit mask so loop2 skips dead chunks without recomputing dd/vote.
template <int MODE>
__global__ void __launch_bounds__(256, 4) passA_kernel(
    const float* __restrict__ xyz1, const float* __restrict__ xyz2,
    float l2new, float l2old)
{
    __shared__ float4 sm_pt4[MM];    // {x, y, z, remainR}
    __shared__ float  sm_cr[MM];     // ccrr

    const int b = blockIdx.y;
    const int t = threadIdx.x, warp = t >> 5, lane = t & 31;
    const int row0 = blockIdx.x * ROWS_PB + warp * RPW;

    // stage column data (one barrier total)
    for (int idx = t; idx < MM; idx += 256) {
        const float* p2 = xyz2 + ((size_t)b * MM + idx) * 3;
        sm_pt4[idx] = make_float4(p2[0], p2[1], p2[2], g_remainR[b * MM + idx]);
        sm_cr[idx] = g_ccrr[b * MM + idx];
    }
    __syncthreads();

    // this warp's rows: packed negated coordinates (pairs (0,1) and (2,3))
    float scaleP[RPW];
    float xs[RPW], ys[RPW], zs[RPW];
    bool hasPrev = false;
#pragma unroll
    for (int r = 0; r < RPW; r++) {
        const float* p1 = xyz1 + ((size_t)b * NN + row0 + r) * 3;
        xs[r] = -p1[0]; ys[r] = -p1[1]; zs[r] = -p1[2];
        scaleP[r] = g_scaleP[b * NN + row0 + r];
        if (scaleP[r] != 0.f) hasPrev = true;
    }
    const u64 nx01 = pack2(xs[0], xs[1]), nx23 = pack2(xs[2], xs[3]);
    const u64 ny01 = pack2(ys[0], ys[1]), ny23 = pack2(ys[2], ys[3]);
    const u64 nz01 = pack2(zs[0], zs[1]), nz23 = pack2(zs[2], zs[3]);
    const u64 l2n2 = pack2(l2new, l2new);
    const u64 l2o2 = pack2(l2old, l2old);

    u64 srow01 = 0ull, srow23 = 0ull, rdp01 = 0ull, rdp23 = 0ull;  // (0.f,0.f)
    u64 aliveMask = 0ull;
    float racc = 0.f;                      // ZERO mode: sum(rr) shared by all rows

    // ---- loop 1: new-level row sums + old-level deferred decrement ----------
    for (int c = 0; c < MM; c += 32) {
        const int col = c + lane;
        const float4 pt = sm_pt4[col];
        const u64 bx2 = pack2(pt.x, pt.x);
        const u64 by2 = pack2(pt.y, pt.y);
        const u64 bz2 = pack2(pt.z, pt.z);

        u64 dd01, dd23;
        {
            u64 dx = add2(bx2, nx01), dy = add2(by2, ny01), dz = add2(bz2, nz01);
            dd01 = fma2(dz, dz, fma2(dy, dy, mul2(dx, dx)));
            dx = add2(bx2, nx23); dy = add2(by2, ny23); dz = add2(bz2, nz23);
            dd23 = fma2(dz, dz, fma2(dy, dy, mul2(dx, dx)));
        }

        if (MODE == MODE_ZERO) {
            racc += pt.w;
            // old level computed directly (e_new == 1 here, ^4 trick unusable)
            if (hasPrev) {
                float b0, b1, b2, b3;
                unpack2(mul2(dd01, l2o2), b0, b1);
                unpack2(mul2(dd23, l2o2), b2, b3);
                const u64 e01 = pack2(ex2f(b0), ex2f(b1));
                const u64 e23 = pack2(ex2f(b2), ex2f(b3));
                const float lcr = sm_cr[col];
                const u64 lcr2 = pack2(lcr, lcr);
                rdp01 = fma2(e01, lcr2, rdp01);
                rdp23 = fma2(e23, lcr2, rdp23);
            }
        } else {
            float a0, a1, a2, a3;
            unpack2(mul2(dd01, l2n2), a0, a1);
            unpack2(mul2(dd23, l2n2), a2, a3);
            bool act = true;
            if (MODE == MODE_SKIP) {
                float amax = fmaxf(fmaxf(a0, a1), fmaxf(a2, a3));
                act = __any_sync(0xffffffffu, amax > -126.f);
            }
            if (act) {
                if (MODE == MODE_SKIP) aliveMask |= 1ull << (c >> 5);
                const u64 e01 = pack2(ex2f(a0), ex2f(a1));
                const u64 e23 = pack2(ex2f(a2), ex2f(a3));
                const u64 lrr2 = pack2(pt.w, pt.w);
                srow01 = fma2(e01, lrr2, srow01);
                srow23 = fma2(e23, lrr2, srow23);
                if (hasPrev) {
                    const float lcr = sm_cr[col];
                    const u64 lcr2 = pack2(lcr, lcr);
                    u64 q01 = mul2(e01, e01); q01 = mul2(q01, q01);
                    u64 q23 = mul2(e23, e23); q23 = mul2(q23, q23);
                    rdp01 = fma2(q01, lcr2, rdp01);
                    rdp23 = fma2(q23, lcr2, rdp23);
                }
            }
        }
    }

    float srow[RPW], rdp[RPW];
    unpack2(srow01, srow[0], srow[1]);
    unpack2(srow23, srow[2], srow[3]);
    unpack2(rdp01, rdp[0], rdp[1]);
    unpack2(rdp23, rdp[2], rdp[3]);
    if (MODE == MODE_ZERO) {
#pragma unroll
        for (int r = 0; r < RPW; r++) srow[r] = racc;
    }

    // ---- warp-only reduction (butterfly -> all lanes hold the sums) ---------
#pragma unroll
    for (int off = 16; off > 0; off >>= 1) {
#pragma unroll
        for (int r = 0; r < RPW; r++) {
            srow[r] += __shfl_xor_sync(0xffffffffu, srow[r], off);
            rdp[r]  += __shfl_xor_sync(0xffffffffu, rdp[r],  off);
        }
    }

    float scaleEff[RPW];
    bool anyAct = false;
#pragma unroll
    for (int r = 0; r < RPW; r++) {
        const int li = b * NN + row0 + r;
        float rl = fmaxf(g_remainL[li] - scaleP[r] * rdp[r], 0.f);
        float sc = rl / (srow[r] + EPSv);
        const bool act = (srow[r] != 0.f);
        scaleEff[r] = act ? sc : 0.f;      // 0 => exact-zero contributions
        if (act) anyAct = true;
        if (lane == 0) {
            g_remainL[li] = rl;
            g_scaleP[li] = act ? sc : 0.f;
        }
    }

    if (!anyAct) return;   // whole warp: nothing to accumulate

    const u64 sc01 = pack2(scaleEff[0], scaleEff[1]);
    const u64 sc23 = pack2(scaleEff[2], scaleEff[3]);
    const u64 ONE2 = pack2(1.f, 1.f);

    // ---- loop 2: recompute e (bit-identical), scale, column partials --------
    for (int c = 0; c < MM; c += 32) {
        if (MODE == MODE_SKIP && !((aliveMask >> (c >> 5)) & 1ull)) continue;

        const int col = c + lane;
        const float4 pt = sm_pt4[col];
        const u64 bx2 = pack2(pt.x, pt.x);
        const u64 by2 = pack2(pt.y, pt.y);
        const u64 bz2 = pack2(pt.z, pt.z);

        u64 dd01, dd23;
        {
            u64 dx = add2(bx2, nx01), dy = add2(by2, ny01), dz = add2(bz2, nz01);
            dd01 = fma2(dz, dz, fma2(dy, dy, mul2(dx, dx)));
            dx = add2(bx2, nx23); dy = add2(by2, ny23); dz = add2(bz2, nz23);
            dd23 = fma2(dz, dz, fma2(dy, dy, mul2(dx, dx)));
        }

        u64 e01, e23;
        if (MODE == MODE_ZERO) {
            e01 = ONE2; e23 = ONE2;
        } else {
            float a0, a1, a2, a3;
            unpack2(mul2(dd01, l2n2), a0, a1);
            unpack2(mul2(dd23, l2n2), a2, a3);
            e01 = pack2(ex2f(a0), ex2f(a1));
            e23 = pack2(ex2f(a2), ex2f(a3));
        }

        const u64 lrr2 = pack2(pt.w, pt.w);
        const u64 w01 = mul2(mul2(e01, lrr2), sc01);
        const u64 w23 = mul2(mul2(e23, lrr2), sc23);

        float wl, wh;
        unpack2(add2(w01, w23), wl, wh);
        const float csum = wl + wh;

        float d0, d1, d2v, d3;
        unpack2(dd01, d0, d1);
        unpack2(dd23, d2v, d3);
        const u64 s01 = pack2(sqrt_approx(d0), sqrt_approx(d1));
        const u64 s23 = pack2(sqrt_approx(d2v), sqrt_approx(d3));

        float cl, ch;
        unpack2(fma2(w23, s23, mul2(w01, s01)), cl, ch);
        const float ccost = cl + ch;

        red_add_v2(&g_colacc[b * MM + col], csum, ccost);
    }
}

// Column saturation + remainR update + cost accumulation; stores ccrr =
// cons * remainR_prev for the next iteration's deferred remainL decrement.
__global__ void __launch_bounds__(256) cons_kernel(float* __restrict__ out) {
    const int b = blockIdx.y;
    const int l = blockIdx.x * 256 + threadIdx.x;
    const int idx = b * MM + l;

    float2 acc = g_colacc[idx];
    float sr  = acc.x;
    float rrv = g_remainR[idx];
    float c = fminf(rrv / (sr + EPSv), 1.0f);
    g_ccrr[idx] = c * rrv;
    g_remainR[idx] = fmaxf(rrv - sr * c, 0.f);
    float local = c * acc.y;
    g_colacc[idx] = make_float2(0.f, 0.f);

#pragma unroll
    for (int off = 16; off > 0; off >>= 1)
        local += __shfl_xor_sync(0xffffffffu, local, off);

    __shared__ float red[8];
    const int warp = threadIdx.x >> 5, lane = threadIdx.x & 31;
    if (lane == 0) red[warp] = local;
    __syncthreads();
    if (threadIdx.x == 0) {
        float s = 0.f;
#pragma unroll
        for (int w = 0; w < 8; w++) s += red[w];
        atomicAdd(&out[b], s);
    }
}

// ---------------------------------------------------------------------------
extern "C" void kernel_launch(void* const* d_in, const int* in_sizes, int n_in,
                              void* d_out, int out_size) {
    (void)in_sizes; (void)n_in; (void)out_size;
    const float* xyz1 = (const float*)d_in[0];
    const float* xyz2 = (const float*)d_in[1];
    float* out = (float*)d_out;

    const float mx = (float)(NN > MM ? NN : MM);
    init_kernel<<<(BB * MM + 255) / 256, 256>>>(out, mx / (float)NN, mx / (float)MM);

    const float LOG2E = 1.4426950408889634f;
    dim3 grid(NN / ROWS_PB, BB);     // (64, 16) = 1024 blocks
    dim3 cgrid(MM / 256, BB);        // (8, 16) = 128 blocks

    float l2old = 0.f;
    for (int j = 7; j >= -2; --j) {
        float level = (j == -2) ? 0.f : -powf(4.f, (float)j);
        float l2new = level * LOG2E;

        if (j == -2) {
            passA_kernel<MODE_ZERO><<<grid, 256>>>(xyz1, xyz2, 0.f, l2old);
        } else if (level < -200.f) {
            passA_kernel<MODE_SKIP><<<grid, 256>>>(xyz1, xyz2, l2new, l2old);
        } else {
            passA_kernel<MODE_NORM><<<grid, 256>>>(xyz1, xyz2, l2new, l2old);
        }
        cons_kernel<<<cgrid, 256>>>(out);

        l2old = l2new;
    }
}

// round 13
// speedup vs baseline: 7.1464x; 1.0371x over previous
#include <cuda_runtime.h>
#include <math.h>

// Problem shape (fixed by the dataset): xyz1 (16,2048,3), xyz2 (16,2048,3)
#define BB 16
#define NN 2048
#define MM 2048
#define RPW 4                 // rows per warp (2 f32x2 pairs)
#define WPB 8                 // warps per block (256 threads)
#define ROWS_PB (RPW * WPB)   // 32 rows per block
#define NCHUNK (MM / 32)      // 64 column chunks

constexpr float EPSv = 1e-9f;

// -------- device scratch (vectors only; NO matrix scratch) ------------------
__device__ float  g_remainL[BB * NN];
__device__ float  g_scaleP[BB * NN];   // scale_i of previous iteration (0 if row sum was 0)
__device__ float  g_remainR[BB * MM];
__device__ float  g_ccrr[BB * MM];     // cons * remainR_prev of previous iteration
__device__ float2 g_colacc[BB * MM];   // .x = col sum of w', .y = col sum of w'*sqrt(d2)
__device__ float4 g_xyz1s[BB * NN];    // Morton-sorted row points
__device__ float4 g_xyz2s[BB * MM];    // Morton-sorted column points
__device__ float4 g_cbox[BB * NCHUNK]; // per-column-chunk bounding sphere {cx,cy,cz,R}

typedef unsigned long long u64;

__device__ __forceinline__ float ex2f(float x) {
    float y; asm("ex2.approx.ftz.f32 %0, %1;" : "=f"(y) : "f"(x)); return y;
}
__device__ __forceinline__ float sqrt_approx(float x) {
    float y; asm("sqrt.approx.ftz.f32 %0, %1;" : "=f"(y) : "f"(x)); return y;
}
__device__ __forceinline__ u64 pack2(float lo, float hi) {
    u64 r;
    asm("mov.b64 %0, {%1, %2};" : "=l"(r)
        : "r"(__float_as_uint(lo)), "r"(__float_as_uint(hi)));
    return r;
}
__device__ __forceinline__ void unpack2(u64 v, float& lo, float& hi) {
    unsigned a, b;
    asm("mov.b64 {%0, %1}, %2;" : "=r"(a), "=r"(b) : "l"(v));
    lo = __uint_as_float(a); hi = __uint_as_float(b);
}
__device__ __forceinline__ u64 add2(u64 a, u64 b) {
    u64 r; asm("add.rn.f32x2 %0, %1, %2;" : "=l"(r) : "l"(a), "l"(b)); return r;
}
__device__ __forceinline__ u64 mul2(u64 a, u64 b) {
    u64 r; asm("mul.rn.f32x2 %0, %1, %2;" : "=l"(r) : "l"(a), "l"(b)); return r;
}
__device__ __forceinline__ u64 fma2(u64 a, u64 b, u64 c) {
    u64 r; asm("fma.rn.f32x2 %0, %1, %2, %3;" : "=l"(r) : "l"(a), "l"(b), "l"(c)); return r;
}
__device__ __forceinline__ void red_add_v2(float2* p, float a, float b) {
    asm volatile("red.global.add.v2.f32 [%0], {%1, %2};"
                 :: "l"(p), "f"(a), "f"(b) : "memory");
}
__device__ __forceinline__ unsigned expand10(unsigned v) {
    v &= 0x3FFu;
    v = (v | (v << 16)) & 0x030000FFu;
    v = (v | (v << 8))  & 0x0300F00Fu;
    v = (v | (v << 4))  & 0x030C30C3u;
    v = (v | (v << 2))  & 0x09249249u;
    return v;
}

// ---------------------------------------------------------------------------
__global__ void init_kernel(float* __restrict__ out, float initL, float initR) {
    int idx = blockIdx.x * blockDim.x + threadIdx.x;
    if (idx < BB * NN) { g_remainL[idx] = initL; g_scaleP[idx] = 0.f; }
    if (idx < BB * MM) { g_remainR[idx] = initR; g_ccrr[idx] = 0.f;
                         g_colacc[idx] = make_float2(0.f, 0.f); }
    if (idx < BB) out[idx] = 0.f;
}

// Morton sort of one side (rows or columns) of one batch. Bitonic sort of
// 2048 packed keys (morton30 << 16 | index) in shared memory; writes the
// sorted coordinates (gather) and, for the column side, per-32-col chunk
// bounding spheres. Output is a pure permutation: the algorithm operates in
// sorted index space throughout (state is internal; result is a sum).
__global__ void __launch_bounds__(1024) sort_kernel(
    const float* __restrict__ xyz1, const float* __restrict__ xyz2)
{
    const int b = blockIdx.y;
    const int side = blockIdx.x;   // 0: rows (xyz1), 1: cols (xyz2)
    const int N = 2048;
    const float* src = side ? (xyz2 + (size_t)b * MM * 3) : (xyz1 + (size_t)b * NN * 3);
    float4* dst = side ? (g_xyz2s + b * MM) : (g_xyz1s + b * NN);

    __shared__ u64 key[2048];
    const int t = threadIdx.x;
    for (int i = t; i < N; i += 1024) {
        float x = src[3*i], y = src[3*i+1], z = src[3*i+2];
        unsigned ux = (unsigned)fminf(1023.f, fmaxf(0.f, (x + 6.f) * 85.25f));
        unsigned uy = (unsigned)fminf(1023.f, fmaxf(0.f, (y + 6.f) * 85.25f));
        unsigned uz = (unsigned)fminf(1023.f, fmaxf(0.f, (z + 6.f) * 85.25f));
        unsigned code = expand10(ux) | (expand10(uy) << 1) | (expand10(uz) << 2);
        key[i] = ((u64)code << 16) | (unsigned)i;
    }
    __syncthreads();
    for (int kk = 2; kk <= N; kk <<= 1) {
        for (int jj = kk >> 1; jj > 0; jj >>= 1) {
            for (int i = t; i < N; i += 1024) {
                int ixj = i ^ jj;
                if (ixj > i) {
                    u64 a = key[i], c = key[ixj];
                    if (((i & kk) == 0) == (a > c)) { key[i] = c; key[ixj] = a; }
                }
            }
            __syncthreads();
        }
    }
    for (int i = t; i < N; i += 1024) {
        int si = (int)(key[i] & 0xFFFFull);
        dst[i] = make_float4(src[3*si], src[3*si+1], src[3*si+2], 0.f);
    }
    if (side) {
        const int warp = t >> 5, lane = t & 31;
        for (int ch = warp; ch < NCHUNK; ch += 32) {
            int si = (int)(key[ch * 32 + lane] & 0xFFFFull);
            float x = src[3*si], y = src[3*si+1], z = src[3*si+2];
            float mnx = x, mxx = x, mny = y, mxy = y, mnz = z, mxz = z;
#pragma unroll
            for (int off = 16; off > 0; off >>= 1) {
                mnx = fminf(mnx, __shfl_xor_sync(0xffffffffu, mnx, off));
                mxx = fmaxf(mxx, __shfl_xor_sync(0xffffffffu, mxx, off));
                mny = fminf(mny, __shfl_xor_sync(0xffffffffu, mny, off));
                mxy = fmaxf(mxy, __shfl_xor_sync(0xffffffffu, mxy, off));
                mnz = fminf(mnz, __shfl_xor_sync(0xffffffffu, mnz, off));
                mxz = fmaxf(mxz, __shfl_xor_sync(0xffffffffu, mxz, off));
            }
            if (lane == 0) {
                float hx = 0.5f * (mxx - mnx), hy = 0.5f * (mxy - mny), hz = 0.5f * (mxz - mnz);
                g_cbox[b * NCHUNK + ch] = make_float4(
                    0.5f * (mnx + mxx), 0.5f * (mny + mxy), 0.5f * (mnz + mxz),
                    sqrtf(hx*hx + hy*hy + hz*hz));
            }
        }
    }
}

#define MODE_SKIP 1
#define MODE_ZERO 2

// One annealing iteration, warp-autonomous, zero matrix traffic, sorted space.
// Bounding-sphere pre-test (2 ballots -> 64-bit chunk mask) skips chunks whose
// exps ALL underflow to exact 0 (FTZ), bit-identical to computing them.
// Old-level exp = e_new^4 (schedule: l2old == 4*l2new; FTZ boundaries coincide).
template <int MODE>
__global__ void __launch_bounds__(256, 4) passA_kernel(
    float l2new, float l2old, float sqrtThr)
{
    __shared__ float4 sm_pt4[MM];        // {x, y, z, remainR}
    __shared__ float  sm_cr[MM];         // ccrr
    __shared__ float4 sm_cbox[NCHUNK];

    const int b = blockIdx.y;
    const int t = threadIdx.x, warp = t >> 5, lane = t & 31;
    const int row0 = blockIdx.x * ROWS_PB + warp * RPW;

    for (int idx = t; idx < MM; idx += 256) {
        float4 p = g_xyz2s[b * MM + idx];
        p.w = g_remainR[b * MM + idx];
        sm_pt4[idx] = p;
        sm_cr[idx] = g_ccrr[b * MM + idx];
    }
    if (t < NCHUNK) sm_cbox[t] = g_cbox[b * NCHUNK + t];
    __syncthreads();

    // this warp's rows (sorted space): packed negated coords + bbox
    float4 rp0 = g_xyz1s[b * NN + row0 + 0];
    float4 rp1 = g_xyz1s[b * NN + row0 + 1];
    float4 rp2 = g_xyz1s[b * NN + row0 + 2];
    float4 rp3 = g_xyz1s[b * NN + row0 + 3];
    const u64 nx01 = pack2(-rp0.x, -rp1.x), nx23 = pack2(-rp2.x, -rp3.x);
    const u64 ny01 = pack2(-rp0.y, -rp1.y), ny23 = pack2(-rp2.y, -rp3.y);
    const u64 nz01 = pack2(-rp0.z, -rp1.z), nz23 = pack2(-rp2.z, -rp3.z);
    const u64 l2n2 = pack2(l2new, l2new);
    const u64 l2o2 = pack2(l2old, l2old);

    float scaleP[RPW];
    bool hasPrev = false;
#pragma unroll
    for (int r = 0; r < RPW; r++) {
        scaleP[r] = g_scaleP[b * NN + row0 + r];
        if (scaleP[r] != 0.f) hasPrev = true;
    }

    u64 boxAlive = ~0ull;
    if (MODE == MODE_SKIP && sqrtThr < 8.f) {
        float mnx = fminf(fminf(rp0.x, rp1.x), fminf(rp2.x, rp3.x));
        float mxx = fmaxf(fmaxf(rp0.x, rp1.x), fmaxf(rp2.x, rp3.x));
        float mny = fminf(fminf(rp0.y, rp1.y), fminf(rp2.y, rp3.y));
        float mxy = fmaxf(fmaxf(rp0.y, rp1.y), fmaxf(rp2.y, rp3.y));
        float mnz = fminf(fminf(rp0.z, rp1.z), fminf(rp2.z, rp3.z));
        float mxz = fmaxf(fmaxf(rp0.z, rp1.z), fmaxf(rp2.z, rp3.z));
        float rcx = 0.5f * (mnx + mxx), hx = 0.5f * (mxx - mnx);
        float rcy = 0.5f * (mny + mxy), hy = 0.5f * (mxy - mny);
        float rcz = 0.5f * (mnz + mxz), hz = 0.5f * (mxz - mnz);
        float Rplus = sqrt_approx(hx*hx + hy*hy + hz*hz) + sqrtThr + 0.02f;

        float4 cb = sm_cbox[lane];
        float dx = rcx - cb.x, dy = rcy - cb.y, dz = rcz - cb.z;
        float lim = cb.w + Rplus;
        unsigned lo = __ballot_sync(0xffffffffu, dx*dx + dy*dy + dz*dz <= lim*lim);
        cb = sm_cbox[32 + lane];
        dx = rcx - cb.x; dy = rcy - cb.y; dz = rcz - cb.z;
        lim = cb.w + Rplus;
        unsigned hi = __ballot_sync(0xffffffffu, dx*dx + dy*dy + dz*dz <= lim*lim);
        boxAlive = ((u64)hi << 32) | lo;
    }

    u64 srow01 = 0ull, srow23 = 0ull, rdp01 = 0ull, rdp23 = 0ull;  // (0.f,0.f)
    u64 aliveMask = 0ull;
    float racc = 0.f;                      // ZERO mode: sum(rr) shared by all rows

    // ---- loop 1: new-level row sums + old-level deferred decrement ----------
    for (int c = 0; c < MM; c += 32) {
        if (MODE == MODE_SKIP && !((boxAlive >> (c >> 5)) & 1ull)) continue;

        const int col = c + lane;
        const float4 pt = sm_pt4[col];
        const u64 bx2 = pack2(pt.x, pt.x);
        const u64 by2 = pack2(pt.y, pt.y);
        const u64 bz2 = pack2(pt.z, pt.z);

        u64 dd01, dd23;
        {
            u64 dx = add2(bx2, nx01), dy = add2(by2, ny01), dz = add2(bz2, nz01);
            dd01 = fma2(dz, dz, fma2(dy, dy, mul2(dx, dx)));
            dx = add2(bx2, nx23); dy = add2(by2, ny23); dz = add2(bz2, nz23);
            dd23 = fma2(dz, dz, fma2(dy, dy, mul2(dx, dx)));
        }

        if (MODE == MODE_ZERO) {
            racc += pt.w;
            if (hasPrev) {       // old level direct (e_new == 1 here)
                float b0, b1, b2, b3;
                unpack2(mul2(dd01, l2o2), b0, b1);
                unpack2(mul2(dd23, l2o2), b2, b3);
                const u64 e01 = pack2(ex2f(b0), ex2f(b1));
                const u64 e23 = pack2(ex2f(b2), ex2f(b3));
                const float lcr = sm_cr[col];
                const u64 lcr2 = pack2(lcr, lcr);
                rdp01 = fma2(e01, lcr2, rdp01);
                rdp23 = fma2(e23, lcr2, rdp23);
            }
        } else {
            float a0, a1, a2, a3;
            unpack2(mul2(dd01, l2n2), a0, a1);
            unpack2(mul2(dd23, l2n2), a2, a3);
            float amax = fmaxf(fmaxf(a0, a1), fmaxf(a2, a3));
            if (__any_sync(0xffffffffu, amax > -126.f)) {
                aliveMask |= 1ull << (c >> 5);
                const u64 e01 = pack2(ex2f(a0), ex2f(a1));
                const u64 e23 = pack2(ex2f(a2), ex2f(a3));
                const u64 lrr2 = pack2(pt.w, pt.w);
                srow01 = fma2(e01, lrr2, srow01);
                srow23 = fma2(e23, lrr2, srow23);
                if (hasPrev) {
                    const float lcr = sm_cr[col];
                    const u64 lcr2 = pack2(lcr, lcr);
                    u64 q01 = mul2(e01, e01); q01 = mul2(q01, q01);
                    u64 q23 = mul2(e23, e23); q23 = mul2(q23, q23);
                    rdp01 = fma2(q01, lcr2, rdp01);
                    rdp23 = fma2(q23, lcr2, rdp23);
                }
            }
        }
    }

    float srow[RPW], rdp[RPW];
    unpack2(srow01, srow[0], srow[1]);
    unpack2(srow23, srow[2], srow[3]);
    unpack2(rdp01, rdp[0], rdp[1]);
    unpack2(rdp23, rdp[2], rdp[3]);
    if (MODE == MODE_ZERO) {
#pragma unroll
        for (int r = 0; r < RPW; r++) srow[r] = racc;
    }

    // ---- warp-only reduction (butterfly -> all lanes hold the sums) ---------
#pragma unroll
    for (int off = 16; off > 0; off >>= 1) {
#pragma unroll
        for (int r = 0; r < RPW; r++) {
            srow[r] += __shfl_xor_sync(0xffffffffu, srow[r], off);
            rdp[r]  += __shfl_xor_sync(0xffffffffu, rdp[r],  off);
        }
    }

    float scaleEff[RPW];
    bool anyAct = false;
#pragma unroll
    for (int r = 0; r < RPW; r++) {
        const int li = b * NN + row0 + r;
        float rl = fmaxf(g_remainL[li] - scaleP[r] * rdp[r], 0.f);
        float sc = rl / (srow[r] + EPSv);
        const bool act = (srow[r] != 0.f);
        scaleEff[r] = act ? sc : 0.f;      // 0 => exact-zero contributions
        if (act) anyAct = true;
        if (lane == 0) {
            g_remainL[li] = rl;
            g_scaleP[li] = act ? sc : 0.f;
        }
    }

    if (!anyAct) return;

    const u64 sc01 = pack2(scaleEff[0], scaleEff[1]);
    const u64 sc23 = pack2(scaleEff[2], scaleEff[3]);
    const u64 ONE2 = pack2(1.f, 1.f);

    // ---- loop 2: recompute e (bit-identical), scale, column partials --------
    for (int c = 0; c < MM; c += 32) {
        if (MODE == MODE_SKIP && !((aliveMask >> (c >> 5)) & 1ull)) continue;

        const int col = c + lane;
        const float4 pt = sm_pt4[col];
        const u64 bx2 = pack2(pt.x, pt.x);
        const u64 by2 = pack2(pt.y, pt.y);
        const u64 bz2 = pack2(pt.z, pt.z);

        u64 dd01, dd23;
        {
            u64 dx = add2(bx2, nx01), dy = add2(by2, ny01), dz = add2(bz2, nz01);
            dd01 = fma2(dz, dz, fma2(dy, dy, mul2(dx, dx)));
            dx = add2(bx2, nx23); dy = add2(by2, ny23); dz = add2(bz2, nz23);
            dd23 = fma2(dz, dz, fma2(dy, dy, mul2(dx, dx)));
        }

        u64 e01, e23;
        if (MODE == MODE_ZERO) {
            e01 = ONE2; e23 = ONE2;
        } else {
            float a0, a1, a2, a3;
            unpack2(mul2(dd01, l2n2), a0, a1);
            unpack2(mul2(dd23, l2n2), a2, a3);
            e01 = pack2(ex2f(a0), ex2f(a1));
            e23 = pack2(ex2f(a2), ex2f(a3));
        }

        const u64 lrr2 = pack2(pt.w, pt.w);
        const u64 w01 = mul2(mul2(e01, lrr2), sc01);
        const u64 w23 = mul2(mul2(e23, lrr2), sc23);

        float wl, wh;
        unpack2(add2(w01, w23), wl, wh);
        const float csum = wl + wh;

        float d0, d1, d2v, d3;
        unpack2(dd01, d0, d1);
        unpack2(dd23, d2v, d3);
        const u64 s01 = pack2(sqrt_approx(d0), sqrt_approx(d1));
        const u64 s23 = pack2(sqrt_approx(d2v), sqrt_approx(d3));

        float cl, ch;
        unpack2(fma2(w23, s23, mul2(w01, s01)), cl, ch);
        const float ccost = cl + ch;

        red_add_v2(&g_colacc[b * MM + col], csum, ccost);
    }
}

// Column saturation + remainR update + cost accumulation; stores ccrr =
// cons * remainR_prev for the next iteration's deferred remainL decrement.
__global__ void __launch_bounds__(256) cons_kernel(float* __restrict__ out) {
    const int b = blockIdx.y;
    const int l = blockIdx.x * 256 + threadIdx.x;
    const int idx = b * MM + l;

    float2 acc = g_colacc[idx];
    float sr  = acc.x;
    float rrv = g_remainR[idx];
    float c = fminf(rrv / (sr + EPSv), 1.0f);
    g_ccrr[idx] = c * rrv;
    g_remainR[idx] = fmaxf(rrv - sr * c, 0.f);
    float local = c * acc.y;
    g_colacc[idx] = make_float2(0.f, 0.f);

#pragma unroll
    for (int off = 16; off > 0; off >>= 1)
        local += __shfl_xor_sync(0xffffffffu, local, off);

    __shared__ float red[8];
    const int warp = threadIdx.x >> 5, lane = threadIdx.x & 31;
    if (lane == 0) red[warp] = local;
    __syncthreads();
    if (threadIdx.x == 0) {
        float s = 0.f;
#pragma unroll
        for (int w = 0; w < 8; w++) s += red[w];
        atomicAdd(&out[b], s);
    }
}

// ---------------------------------------------------------------------------
extern "C" void kernel_launch(void* const* d_in, const int* in_sizes, int n_in,
                              void* d_out, int out_size) {
    (void)in_sizes; (void)n_in; (void)out_size;
    const float* xyz1 = (const float*)d_in[0];
    const float* xyz2 = (const float*)d_in[1];
    float* out = (float*)d_out;

    const float mx = (float)(NN > MM ? NN : MM);
    init_kernel<<<(BB * MM + 255) / 256, 256>>>(out, mx / (float)NN, mx / (float)MM);
    sort_kernel<<<dim3(2, BB), 1024>>>(xyz1, xyz2);

    const float LOG2E = 1.4426950408889634f;
    dim3 grid(NN / ROWS_PB, BB);     // (64, 16) = 1024 blocks
    dim3 cgrid(MM / 256, BB);        // (8, 16) = 128 blocks

    float l2old = 0.f;
    for (int j = 7; j >= -2; --j) {
        float level = (j == -2) ? 0.f : -powf(4.f, (float)j);
        float l2new = level * LOG2E;

        if (j == -2) {
            passA_kernel<MODE_ZERO><<<grid, 256>>>(0.f, l2old, 1e9f);
        } else {
            float sqrtThr = sqrtf(126.f / (-l2new));
            passA_kernel<MODE_SKIP><<<grid, 256>>>(l2new, l2old, sqrtThr);
        }
        cons_kernel<<<cgrid, 256>>>(out);

        l2old = l2new;
    }
}

// round 14
// speedup vs baseline: 9.1039x; 1.2739x over previous
#include <cuda_runtime.h>
#include <math.h>

// Problem shape (fixed by the dataset): xyz1 (16,2048,3), xyz2 (16,2048,3)
#define BB 16
#define NN 2048
#define MM 2048
#define RPW 4                 // rows per warp (2 f32x2 pairs)
#define WPB 8                 // warps per block (256 threads)
#define ROWS_PB (RPW * WPB)   // 32 rows per block
#define NCHUNK (MM / 32)      // 64 column chunks

constexpr float EPSv = 1e-9f;

// -------- device scratch (vectors only; NO matrix scratch) ------------------
__device__ float  g_remainL[BB * NN];
__device__ float  g_scaleP[BB * NN];   // scale_i of previous iteration (0 if row inactive)
__device__ float  g_remainR[BB * MM];
__device__ float  g_ccrr[BB * MM];     // cons * remainR_prev of previous iteration
__device__ float2 g_colacc[BB * MM];   // .x = col sum of w', .y = col sum of w'*sqrt(d2)
__device__ float4 g_xyz1s[BB * NN];    // Morton-sorted row points
__device__ float4 g_xyz2s[BB * MM];    // Morton-sorted column points
__device__ float4 g_cbox[BB * NCHUNK]; // per-column-chunk bounding sphere {cx,cy,cz,R}

typedef unsigned long long u64;

__device__ __forceinline__ float ex2f(float x) {
    float y; asm("ex2.approx.ftz.f32 %0, %1;" : "=f"(y) : "f"(x)); return y;
}
__device__ __forceinline__ float sqrt_approx(float x) {
    float y; asm("sqrt.approx.ftz.f32 %0, %1;" : "=f"(y) : "f"(x)); return y;
}
__device__ __forceinline__ u64 pack2(float lo, float hi) {
    u64 r;
    asm("mov.b64 %0, {%1, %2};" : "=l"(r)
        : "r"(__float_as_uint(lo)), "r"(__float_as_uint(hi)));
    return r;
}
__device__ __forceinline__ void unpack2(u64 v, float& lo, float& hi) {
    unsigned a, b;
    asm("mov.b64 {%0, %1}, %2;" : "=r"(a), "=r"(b) : "l"(v));
    lo = __uint_as_float(a); hi = __uint_as_float(b);
}
__device__ __forceinline__ u64 add2(u64 a, u64 b) {
    u64 r; asm("add.rn.f32x2 %0, %1, %2;" : "=l"(r) : "l"(a), "l"(b)); return r;
}
__device__ __forceinline__ u64 mul2(u64 a, u64 b) {
    u64 r; asm("mul.rn.f32x2 %0, %1, %2;" : "=l"(r) : "l"(a), "l"(b)); return r;
}
__device__ __forceinline__ u64 fma2(u64 a, u64 b, u64 c) {
    u64 r; asm("fma.rn.f32x2 %0, %1, %2, %3;" : "=l"(r) : "l"(a), "l"(b), "l"(c)); return r;
}
__device__ __forceinline__ void red_add_v2(float2* p, float a, float b) {
    asm volatile("red.global.add.v2.f32 [%0], {%1, %2};"
                 :: "l"(p), "f"(a), "f"(b) : "memory");
}
__device__ __forceinline__ unsigned expand10(unsigned v) {
    v &= 0x3FFu;
    v = (v | (v << 16)) & 0x030000FFu;
    v = (v | (v << 8))  & 0x0300F00Fu;
    v = (v | (v << 4))  & 0x030C30C3u;
    v = (v | (v << 2))  & 0x09249249u;
    return v;
}

// ---------------------------------------------------------------------------
__global__ void init_kernel(float* __restrict__ out, float initL, float initR) {
    int idx = blockIdx.x * blockDim.x + threadIdx.x;
    if (idx < BB * NN) { g_remainL[idx] = initL; g_scaleP[idx] = 0.f; }
    if (idx < BB * MM) { g_remainR[idx] = initR; g_ccrr[idx] = 0.f;
                         g_colacc[idx] = make_float2(0.f, 0.f); }
    if (idx < BB) out[idx] = 0.f;
}

// Morton sort (bitonic, 2048 keys in smem) of one side of one batch.
// Writes sorted coords; column side also writes per-32-col bounding spheres.
// Pure permutation: all state is internal, output is a permutation-invariant sum.
__global__ void __launch_bounds__(1024) sort_kernel(
    const float* __restrict__ xyz1, const float* __restrict__ xyz2)
{
    const int b = blockIdx.y;
    const int side = blockIdx.x;   // 0: rows (xyz1), 1: cols (xyz2)
    const int N = 2048;
    const float* src = side ? (xyz2 + (size_t)b * MM * 3) : (xyz1 + (size_t)b * NN * 3);
    float4* dst = side ? (g_xyz2s + b * MM) : (g_xyz1s + b * NN);

    __shared__ u64 key[2048];
    const int t = threadIdx.x;
    for (int i = t; i < N; i += 1024) {
        float x = src[3*i], y = src[3*i+1], z = src[3*i+2];
        unsigned ux = (unsigned)fminf(1023.f, fmaxf(0.f, (x + 6.f) * 85.25f));
        unsigned uy = (unsigned)fminf(1023.f, fmaxf(0.f, (y + 6.f) * 85.25f));
        unsigned uz = (unsigned)fminf(1023.f, fmaxf(0.f, (z + 6.f) * 85.25f));
        unsigned code = expand10(ux) | (expand10(uy) << 1) | (expand10(uz) << 2);
        key[i] = ((u64)code << 16) | (unsigned)i;
    }
    __syncthreads();
    for (int kk = 2; kk <= N; kk <<= 1) {
        for (int jj = kk >> 1; jj > 0; jj >>= 1) {
            for (int i = t; i < N; i += 1024) {
                int ixj = i ^ jj;
                if (ixj > i) {
                    u64 a = key[i], c = key[ixj];
                    if (((i & kk) == 0) == (a > c)) { key[i] = c; key[ixj] = a; }
                }
            }
            __syncthreads();
        }
    }
    for (int i = t; i < N; i += 1024) {
        int si = (int)(key[i] & 0xFFFFull);
        dst[i] = make_float4(src[3*si], src[3*si+1], src[3*si+2], 0.f);
    }
    if (side) {
        const int warp = t >> 5, lane = t & 31;
        for (int ch = warp; ch < NCHUNK; ch += 32) {
            int si = (int)(key[ch * 32 + lane] & 0xFFFFull);
            float x = src[3*si], y = src[3*si+1], z = src[3*si+2];
            float mnx = x, mxx = x, mny = y, mxy = y, mnz = z, mxz = z;
#pragma unroll
            for (int off = 16; off > 0; off >>= 1) {
                mnx = fminf(mnx, __shfl_xor_sync(0xffffffffu, mnx, off));
                mxx = fmaxf(mxx, __shfl_xor_sync(0xffffffffu, mxx, off));
                mny = fminf(mny, __shfl_xor_sync(0xffffffffu, mny, off));
                mxy = fmaxf(mxy, __shfl_xor_sync(0xffffffffu, mxy, off));
                mnz = fminf(mnz, __shfl_xor_sync(0xffffffffu, mnz, off));
                mxz = fmaxf(mxz, __shfl_xor_sync(0xffffffffu, mxz, off));
            }
            if (lane == 0) {
                float hx = 0.5f * (mxx - mnx), hy = 0.5f * (mxy - mny), hz = 0.5f * (mxz - mnz);
                g_cbox[b * NCHUNK + ch] = make_float4(
                    0.5f * (mnx + mxx), 0.5f * (mny + mxy), 0.5f * (mnz + mxz),
                    sqrtf(hx*hx + hy*hy + hz*hz));
            }
        }
    }
}

#define MODE_SKIP 1
#define MODE_ZERO 2

// One annealing iteration, warp-autonomous, zero matrix traffic, sorted space.
// Pruning layers (all exact: skipped contributions are exactly 0):
//   chunkRR: columns with remainR==0 (saturated, zeroed in cons)
//   chunkCR: columns with ccrr==0
//   boxN/boxO: bounding-sphere tests at new/old underflow radii (FTZ exact 0)
//   warp exit: all RPW rows fully drained (remainL==0 -> scale 0 -> w==0)
// Old-level exp = e_new^4 (schedule: l2old == 4*l2new; FTZ boundaries coincide).
template <int MODE>
__global__ void __launch_bounds__(256, 4) passA_kernel(
    float l2new, float l2old, float sqrtThrN, float sqrtThrO)
{
    __shared__ float4 sm_pt4[MM];        // {x, y, z, remainR}
    __shared__ float  sm_cr[MM];         // ccrr
    __shared__ float4 sm_cbox[NCHUNK];
    __shared__ unsigned char sm_aRR[NCHUNK], sm_aCR[NCHUNK];
    __shared__ float sm_rsum[WPB];

    const int b = blockIdx.y;
    const int t = threadIdx.x, warp = t >> 5, lane = t & 31;
    const int row0 = blockIdx.x * ROWS_PB + warp * RPW;

    // ---- staging: column data + chunk activity masks + (ZERO) rr block sum --
    float rsum = 0.f;
#pragma unroll
    for (int k = 0; k < 8; k++) {
        const int idx = t + 256 * k;
        float4 p = g_xyz2s[b * MM + idx];
        float rrv = g_remainR[b * MM + idx];
        float crv = g_ccrr[b * MM + idx];
        p.w = rrv;
        sm_pt4[idx] = p;
        sm_cr[idx] = crv;
        rsum += rrv;
        unsigned mr = __ballot_sync(0xffffffffu, rrv != 0.f);
        unsigned mc = __ballot_sync(0xffffffffu, crv != 0.f);
        if (lane == 0) {
            sm_aRR[warp + 8 * k] = (mr != 0u);
            sm_aCR[warp + 8 * k] = (mc != 0u);
        }
    }
    if (MODE == MODE_ZERO) {
#pragma unroll
        for (int off = 16; off > 0; off >>= 1)
            rsum += __shfl_xor_sync(0xffffffffu, rsum, off);
        if (lane == 0) sm_rsum[warp] = rsum;
    }
    if (t < NCHUNK) sm_cbox[t] = g_cbox[b * NCHUNK + t];
    __syncthreads();

    // ---- row state; warp exit if all rows drained ---------------------------
    float remL[RPW], scP[RPW];
    bool hasPrev = false, allZero = true;
#pragma unroll
    for (int r = 0; r < RPW; r++) {
        remL[r] = g_remainL[b * NN + row0 + r];
        scP[r]  = g_scaleP[b * NN + row0 + r];
        if (scP[r] != 0.f) hasPrev = true;
        if (remL[r] != 0.f) allZero = false;
    }
    if (allZero) {
        if (lane == 0) {
#pragma unroll
            for (int r = 0; r < RPW; r++) g_scaleP[b * NN + row0 + r] = 0.f;
        }
        return;
    }

    float4 rp0 = g_xyz1s[b * NN + row0 + 0];
    float4 rp1 = g_xyz1s[b * NN + row0 + 1];
    float4 rp2 = g_xyz1s[b * NN + row0 + 2];
    float4 rp3 = g_xyz1s[b * NN + row0 + 3];
    const u64 nx01 = pack2(-rp0.x, -rp1.x), nx23 = pack2(-rp2.x, -rp3.x);
    const u64 ny01 = pack2(-rp0.y, -rp1.y), ny23 = pack2(-rp2.y, -rp3.y);
    const u64 nz01 = pack2(-rp0.z, -rp1.z), nz23 = pack2(-rp2.z, -rp3.z);
    const u64 l2n2 = pack2(l2new, l2new);
    const u64 l2o2 = pack2(l2old, l2old);

    // ---- chunk masks: saturation + bounding spheres --------------------------
    u64 cRR, cCR;
    {
        unsigned lo = __ballot_sync(0xffffffffu, sm_aRR[lane] != 0);
        unsigned hi = __ballot_sync(0xffffffffu, sm_aRR[32 + lane] != 0);
        cRR = ((u64)hi << 32) | lo;
        lo = __ballot_sync(0xffffffffu, sm_aCR[lane] != 0);
        hi = __ballot_sync(0xffffffffu, sm_aCR[32 + lane] != 0);
        cCR = ((u64)hi << 32) | lo;
    }

    u64 boxN = ~0ull, boxO = ~0ull;
    const bool useN = (MODE != MODE_ZERO) && (sqrtThrN < 8.f);
    const bool useO = hasPrev && (sqrtThrO < 8.f);
    if (useN || useO) {
        float mnx = fminf(fminf(rp0.x, rp1.x), fminf(rp2.x, rp3.x));
        float mxx = fmaxf(fmaxf(rp0.x, rp1.x), fmaxf(rp2.x, rp3.x));
        float mny = fminf(fminf(rp0.y, rp1.y), fminf(rp2.y, rp3.y));
        float mxy = fmaxf(fmaxf(rp0.y, rp1.y), fmaxf(rp2.y, rp3.y));
        float mnz = fminf(fminf(rp0.z, rp1.z), fminf(rp2.z, rp3.z));
        float mxz = fmaxf(fmaxf(rp0.z, rp1.z), fmaxf(rp2.z, rp3.z));
        float rcx = 0.5f * (mnx + mxx), hx = 0.5f * (mxx - mnx);
        float rcy = 0.5f * (mny + mxy), hy = 0.5f * (mxy - mny);
        float rcz = 0.5f * (mnz + mxz), hz = 0.5f * (mxz - mnz);
        float Rrow = sqrt_approx(hx*hx + hy*hy + hz*hz) + 0.02f;

        float4 cb = sm_cbox[lane];
        float dx = rcx - cb.x, dy = rcy - cb.y, dz = rcz - cb.z;
        float d2a = dx*dx + dy*dy + dz*dz;
        float limN = cb.w + Rrow + sqrtThrN, limO = cb.w + Rrow + sqrtThrO;
        unsigned loN = __ballot_sync(0xffffffffu, d2a <= limN * limN);
        unsigned loO = __ballot_sync(0xffffffffu, d2a <= limO * limO);
        cb = sm_cbox[32 + lane];
        dx = rcx - cb.x; dy = rcy - cb.y; dz = rcz - cb.z;
        d2a = dx*dx + dy*dy + dz*dz;
        limN = cb.w + Rrow + sqrtThrN; limO = cb.w + Rrow + sqrtThrO;
        unsigned hiN = __ballot_sync(0xffffffffu, d2a <= limN * limN);
        unsigned hiO = __ballot_sync(0xffffffffu, d2a <= limO * limO);
        if (useN) boxN = ((u64)hiN << 32) | loN;
        if (useO) boxO = ((u64)hiO << 32) | loO;
    }

    const u64 maskS = (MODE == MODE_ZERO) ? 0ull : (cRR & boxN);
    const u64 maskR = hasPrev ? (cCR & boxO) : 0ull;
    const u64 maskAny = maskS | maskR;

    u64 srow01 = 0ull, srow23 = 0ull, rdp01 = 0ull, rdp23 = 0ull;  // (0.f,0.f)
    u64 aliveMask = 0ull;

    // ---- loop 1: new-level row sums + old-level deferred decrement ----------
    for (int c = 0; c < MM; c += 32) {
        const int ch = c >> 5;
        if (!((maskAny >> ch) & 1ull)) continue;

        const int col = c + lane;
        const float4 pt = sm_pt4[col];
        const u64 bx2 = pack2(pt.x, pt.x);
        const u64 by2 = pack2(pt.y, pt.y);
        const u64 bz2 = pack2(pt.z, pt.z);

        u64 dd01, dd23;
        {
            u64 dx = add2(bx2, nx01), dy = add2(by2, ny01), dz = add2(bz2, nz01);
            dd01 = fma2(dz, dz, fma2(dy, dy, mul2(dx, dx)));
            dx = add2(bx2, nx23); dy = add2(by2, ny23); dz = add2(bz2, nz23);
            dd23 = fma2(dz, dz, fma2(dy, dy, mul2(dx, dx)));
        }

        if (MODE == MODE_ZERO) {
            // rdp-only (maskAny == maskR here); old level direct, never underflows
            float b0, b1, b2, b3;
            unpack2(mul2(dd01, l2o2), b0, b1);
            unpack2(mul2(dd23, l2o2), b2, b3);
            const u64 e01 = pack2(ex2f(b0), ex2f(b1));
            const u64 e23 = pack2(ex2f(b2), ex2f(b3));
            const float lcr = sm_cr[col];
            const u64 lcr2 = pack2(lcr, lcr);
            rdp01 = fma2(e01, lcr2, rdp01);
            rdp23 = fma2(e23, lcr2, rdp23);
        } else {
            const bool bS = (maskS >> ch) & 1ull;
            const bool bR = (maskR >> ch) & 1ull;
            float a0, a1, a2, a3;
            unpack2(mul2(dd01, l2n2), a0, a1);
            unpack2(mul2(dd23, l2n2), a2, a3);
            float amax = fmaxf(fmaxf(a0, a1), fmaxf(a2, a3));
            const float vthr = bS ? -126.f : -31.5f;   // old arg = 4*new arg
            if (__any_sync(0xffffffffu, amax > vthr)) {
                const u64 e01 = pack2(ex2f(a0), ex2f(a1));
                const u64 e23 = pack2(ex2f(a2), ex2f(a3));
                if (bS) {
                    aliveMask |= 1ull << ch;
                    const u64 lrr2 = pack2(pt.w, pt.w);
                    srow01 = fma2(e01, lrr2, srow01);
                    srow23 = fma2(e23, lrr2, srow23);
                }
                if (bR) {
                    const float lcr = sm_cr[col];
                    const u64 lcr2 = pack2(lcr, lcr);
                    u64 q01 = mul2(e01, e01); q01 = mul2(q01, q01);
                    u64 q23 = mul2(e23, e23); q23 = mul2(q23, q23);
                    rdp01 = fma2(q01, lcr2, rdp01);
                    rdp23 = fma2(q23, lcr2, rdp23);
                }
            }
        }
    }

    float srow[RPW], rdp[RPW];
    unpack2(srow01, srow[0], srow[1]);
    unpack2(srow23, srow[2], srow[3]);
    unpack2(rdp01, rdp[0], rdp[1]);
    unpack2(rdp23, rdp[2], rdp[3]);

    // ---- warp-only reduction (butterfly -> all lanes hold the sums) ---------
#pragma unroll
    for (int off = 16; off > 0; off >>= 1) {
#pragma unroll
        for (int r = 0; r < RPW; r++) {
            rdp[r] += __shfl_xor_sync(0xffffffffu, rdp[r], off);
            if (MODE != MODE_ZERO)
                srow[r] += __shfl_xor_sync(0xffffffffu, srow[r], off);
        }
    }
    if (MODE == MODE_ZERO) {
        float raccT = 0.f;
#pragma unroll
        for (int w = 0; w < WPB; w++) raccT += sm_rsum[w];
#pragma unroll
        for (int r = 0; r < RPW; r++) srow[r] = raccT;
    }

    float scaleEff[RPW];
    bool anyAct = false;
#pragma unroll
    for (int r = 0; r < RPW; r++) {
        const int li = b * NN + row0 + r;
        float rl = fmaxf(remL[r] - scP[r] * rdp[r], 0.f);
        if (rl < 1e-6f) rl = 0.f;          // drained row -> exact zero (err <= 1e-6 mass)
        float sc = rl / (srow[r] + EPSv);
        const bool act = (srow[r] != 0.f) && (rl != 0.f);
        scaleEff[r] = act ? sc : 0.f;      // 0 => exact-zero contributions
        if (act) anyAct = true;
        if (lane == 0) {
            g_remainL[li] = rl;
            g_scaleP[li] = act ? sc : 0.f;
        }
    }

    if (!anyAct) return;

    const u64 sc01 = pack2(scaleEff[0], scaleEff[1]);
    const u64 sc23 = pack2(scaleEff[2], scaleEff[3]);
    const u64 ONE2 = pack2(1.f, 1.f);
    const u64 mask2 = (MODE == MODE_ZERO) ? cRR : aliveMask;

    // ---- loop 2: recompute e (bit-identical), scale, column partials --------
    for (int c = 0; c < MM; c += 32) {
        if (!((mask2 >> (c >> 5)) & 1ull)) continue;

        const int col = c + lane;
        const float4 pt = sm_pt4[col];
        const u64 bx2 = pack2(pt.x, pt.x);
        const u64 by2 = pack2(pt.y, pt.y);
        const u64 bz2 = pack2(pt.z, pt.z);

        u64 dd01, dd23;
        {
            u64 dx = add2(bx2, nx01), dy = add2(by2, ny01), dz = add2(bz2, nz01);
            dd01 = fma2(dz, dz, fma2(dy, dy, mul2(dx, dx)));
            dx = add2(bx2, nx23); dy = add2(by2, ny23); dz = add2(bz2, nz23);
            dd23 = fma2(dz, dz, fma2(dy, dy, mul2(dx, dx)));
        }

        u64 e01, e23;
        if (MODE == MODE_ZERO) {
            e01 = ONE2; e23 = ONE2;
        } else {
            float a0, a1, a2, a3;
            unpack2(mul2(dd01, l2n2), a0, a1);
            unpack2(mul2(dd23, l2n2), a2, a3);
            e01 = pack2(ex2f(a0), ex2f(a1));
            e23 = pack2(ex2f(a2), ex2f(a3));
        }

        const u64 lrr2 = pack2(pt.w, pt.w);
        const u64 w01 = mul2(mul2(e01, lrr2), sc01);
        const u64 w23 = mul2(mul2(e23, lrr2), sc23);

        float wl, wh;
        unpack2(add2(w01, w23), wl, wh);
        const float csum = wl + wh;

        float d0, d1, d2v, d3;
        unpack2(dd01, d0, d1);
        unpack2(dd23, d2v, d3);
        const u64 s01 = pack2(sqrt_approx(d0), sqrt_approx(d1));
        const u64 s23 = pack2(sqrt_approx(d2v), sqrt_approx(d3));

        float cl, ch2;
        unpack2(fma2(w23, s23, mul2(w01, s01)), cl, ch2);
        const float ccost = cl + ch2;

        red_add_v2(&g_colacc[b * MM + col], csum, ccost);
    }
}

// Column saturation + remainR update + cost accumulation. Saturated columns
// (cons < 1) get remainR = EXACT 0 (true residual is ~1e-9*rr; error negligible,
// enables exact-zero pruning downstream). Stores ccrr = cons * remainR_prev.
__global__ void __launch_bounds__(256) cons_kernel(float* __restrict__ out) {
    const int b = blockIdx.y;
    const int l = blockIdx.x * 256 + threadIdx.x;
    const int idx = b * MM + l;

    float2 acc = g_colacc[idx];
    float sr  = acc.x;
    float rrv = g_remainR[idx];
    float c = fminf(rrv / (sr + EPSv), 1.0f);
    g_ccrr[idx] = c * rrv;
    g_remainR[idx] = (c < 1.0f) ? 0.f : fmaxf(rrv - sr, 0.f);
    float local = c * acc.y;
    g_colacc[idx] = make_float2(0.f, 0.f);

#pragma unroll
    for (int off = 16; off > 0; off >>= 1)
        local += __shfl_xor_sync(0xffffffffu, local, off);

    __shared__ float red[8];
    const int warp = threadIdx.x >> 5, lane = threadIdx.x & 31;
    if (lane == 0) red[warp] = local;
    __syncthreads();
    if (threadIdx.x == 0) {
        float s = 0.f;
#pragma unroll
        for (int w = 0; w < 8; w++) s += red[w];
        atomicAdd(&out[b], s);
    }
}

// ---------------------------------------------------------------------------
extern "C" void kernel_launch(void* const* d_in, const int* in_sizes, int n_in,
                              void* d_out, int out_size) {
    (void)in_sizes; (void)n_in; (void)out_size;
    const float* xyz1 = (const float*)d_in[0];
    const float* xyz2 = (const float*)d_in[1];
    float* out = (float*)d_out;

    const float mx = (float)(NN > MM ? NN : MM);
    init_kernel<<<(BB * MM + 255) / 256, 256>>>(out, mx / (float)NN, mx / (float)MM);
    sort_kernel<<<dim3(2, BB), 1024>>>(xyz1, xyz2);

    const float LOG2E = 1.4426950408889634f;
    dim3 grid(NN / ROWS_PB, BB);     // (64, 16) = 1024 blocks
    dim3 cgrid(MM / 256, BB);        // (8, 16) = 128 blocks

    float l2old = 0.f;
    for (int j = 7; j >= -2; --j) {
        float level = (j == -2) ? 0.f : -powf(4.f, (float)j);
        float l2new = level * LOG2E;

        if (j == -2) {
            // old level is -1: sqrtThrO = sqrt(126 / (LOG2E*1)) ~ 9.34 (no box)
            passA_kernel<MODE_ZERO><<<grid, 256>>>(0.f, l2old, 1e9f, 1e9f);
        } else {
            float sqrtThrN = sqrtf(126.f / (-l2new));
            float sqrtThrO = sqrtThrN * 0.5f;   // l2old == 4*l2new
            passA_kernel<MODE_SKIP><<<grid, 256>>>(l2new, l2old, sqrtThrN, sqrtThrO);
        }
        cons_kernel<<<cgrid, 256>>>(out);

        l2old = l2new;
    }
}

// round 15
// speedup vs baseline: 9.3868x; 1.0311x over previous
#include <cuda_runtime.h>
#include <math.h>

// Problem shape (fixed by the dataset): xyz1 (16,2048,3), xyz2 (16,2048,3)
#define BB 16
#define NN 2048
#define MM 2048
#define RPW 4                 // rows per warp (2 f32x2 pairs)
#define WPB 8                 // warps per block (256 threads)
#define ROWS_PB (RPW * WPB)   // 32 rows per block
#define NCHUNK (MM / 32)      // 64 column chunks

constexpr float EPSv = 1e-9f;

// -------- device scratch (vectors only; NO matrix scratch) ------------------
__device__ float  g_remainL[BB * NN];
__device__ float  g_scaleP[BB * NN];   // scale_i of previous iteration (0 if row inactive)
__device__ float  g_remainR[BB * MM];
__device__ float  g_ccrr[BB * MM];     // cons * remainR_prev of previous iteration
__device__ float2 g_colacc[BB * MM];   // .x = col sum of w', .y = col sum of w'*sqrt(r2_scaled)
__device__ float4 g_xyz1s[BB * NN];    // Morton-sorted row points
__device__ float4 g_xyz2s[BB * MM];    // Morton-sorted column points
__device__ float4 g_cbox[BB * NCHUNK]; // per-column-chunk bounding sphere {cx,cy,cz,R}

typedef unsigned long long u64;

__device__ __forceinline__ float ex2f_neg(float x) {   // 2^(-x); neg folds into MUFU
    float y; asm("{.reg .f32 t; neg.f32 t, %1; ex2.approx.ftz.f32 %0, t;}"
                 : "=f"(y) : "f"(x));
    return y;
}
__device__ __forceinline__ float ex2f(float x) {
    float y; asm("ex2.approx.ftz.f32 %0, %1;" : "=f"(y) : "f"(x)); return y;
}
__device__ __forceinline__ float sqrt_approx(float x) {
    float y; asm("sqrt.approx.ftz.f32 %0, %1;" : "=f"(y) : "f"(x)); return y;
}
__device__ __forceinline__ u64 pack2(float lo, float hi) {
    u64 r;
    asm("mov.b64 %0, {%1, %2};" : "=l"(r)
        : "r"(__float_as_uint(lo)), "r"(__float_as_uint(hi)));
    return r;
}
__device__ __forceinline__ void unpack2(u64 v, float& lo, float& hi) {
    unsigned a, b;
    asm("mov.b64 {%0, %1}, %2;" : "=r"(a), "=r"(b) : "l"(v));
    lo = __uint_as_float(a); hi = __uint_as_float(b);
}
__device__ __forceinline__ u64 add2(u64 a, u64 b) {
    u64 r; asm("add.rn.f32x2 %0, %1, %2;" : "=l"(r) : "l"(a), "l"(b)); return r;
}
__device__ __forceinline__ u64 mul2(u64 a, u64 b) {
    u64 r; asm("mul.rn.f32x2 %0, %1, %2;" : "=l"(r) : "l"(a), "l"(b)); return r;
}
__device__ __forceinline__ u64 fma2(u64 a, u64 b, u64 c) {
    u64 r; asm("fma.rn.f32x2 %0, %1, %2, %3;" : "=l"(r) : "l"(a), "l"(b), "l"(c)); return r;
}
__device__ __forceinline__ void red_add_v2(float2* p, float a, float b) {
    asm volatile("red.global.add.v2.f32 [%0], {%1, %2};"
                 :: "l"(p), "f"(a), "f"(b) : "memory");
}
__device__ __forceinline__ unsigned expand10(unsigned v) {
    v &= 0x3FFu;
    v = (v | (v << 16)) & 0x030000FFu;
    v = (v | (v << 8))  & 0x0300F00Fu;
    v = (v | (v << 4))  & 0x030C30C3u;
    v = (v | (v << 2))  & 0x09249249u;
    return v;
}

// ---------------------------------------------------------------------------
__global__ void init_kernel(float* __restrict__ out, float initL, float initR) {
    int idx = blockIdx.x * blockDim.x + threadIdx.x;
    if (idx < BB * NN) { g_remainL[idx] = initL; g_scaleP[idx] = 0.f; }
    if (idx < BB * MM) { g_remainR[idx] = initR; g_ccrr[idx] = 0.f;
                         g_colacc[idx] = make_float2(0.f, 0.f); }
    if (idx < BB) out[idx] = 0.f;
}

// Morton sort (bitonic, 2048 keys in smem) of one side of one batch.
// Writes sorted coords; column side also writes per-32-col bounding spheres.
// Pure permutation: all state is internal, output is a permutation-invariant sum.
__global__ void __launch_bounds__(1024) sort_kernel(
    const float* __restrict__ xyz1, const float* __restrict__ xyz2)
{
    const int b = blockIdx.y;
    const int side = blockIdx.x;   // 0: rows (xyz1), 1: cols (xyz2)
    const int N = 2048;
    const float* src = side ? (xyz2 + (size_t)b * MM * 3) : (xyz1 + (size_t)b * NN * 3);
    float4* dst = side ? (g_xyz2s + b * MM) : (g_xyz1s + b * NN);

    __shared__ u64 key[2048];
    const int t = threadIdx.x;
    for (int i = t; i < N; i += 1024) {
        float x = src[3*i], y = src[3*i+1], z = src[3*i+2];
        unsigned ux = (unsigned)fminf(1023.f, fmaxf(0.f, (x + 6.f) * 85.25f));
        unsigned uy = (unsigned)fminf(1023.f, fmaxf(0.f, (y + 6.f) * 85.25f));
        unsigned uz = (unsigned)fminf(1023.f, fmaxf(0.f, (z + 6.f) * 85.25f));
        unsigned code = expand10(ux) | (expand10(uy) << 1) | (expand10(uz) << 2);
        key[i] = ((u64)code << 16) | (unsigned)i;
    }
    __syncthreads();
    for (int kk = 2; kk <= N; kk <<= 1) {
        for (int jj = kk >> 1; jj > 0; jj >>= 1) {
            for (int i = t; i < N; i += 1024) {
                int ixj = i ^ jj;
                if (ixj > i) {
                    u64 a = key[i], c = key[ixj];
                    if (((i & kk) == 0) == (a > c)) { key[i] = c; key[ixj] = a; }
                }
            }
            __syncthreads();
        }
    }
    for (int i = t; i < N; i += 1024) {
        int si = (int)(key[i] & 0xFFFFull);
        dst[i] = make_float4(src[3*si], src[3*si+1], src[3*si+2], 0.f);
    }
    if (side) {
        const int warp = t >> 5, lane = t & 31;
        for (int ch = warp; ch < NCHUNK; ch += 32) {
            int si = (int)(key[ch * 32 + lane] & 0xFFFFull);
            float x = src[3*si], y = src[3*si+1], z = src[3*si+2];
            float mnx = x, mxx = x, mny = y, mxy = y, mnz = z, mxz = z;
#pragma unroll
            for (int off = 16; off > 0; off >>= 1) {
                mnx = fminf(mnx, __shfl_xor_sync(0xffffffffu, mnx, off));
                mxx = fmaxf(mxx, __shfl_xor_sync(0xffffffffu, mxx, off));
                mny = fminf(mny, __shfl_xor_sync(0xffffffffu, mny, off));
                mxy = fmaxf(mxy, __shfl_xor_sync(0xffffffffu, mxy, off));
                mnz = fminf(mnz, __shfl_xor_sync(0xffffffffu, mnz, off));
                mxz = fmaxf(mxz, __shfl_xor_sync(0xffffffffu, mxz, off));
            }
            if (lane == 0) {
                float hx = 0.5f * (mxx - mnx), hy = 0.5f * (mxy - mny), hz = 0.5f * (mxz - mnz);
                g_cbox[b * NCHUNK + ch] = make_float4(
                    0.5f * (mnx + mxx), 0.5f * (mny + mxy), 0.5f * (mnz + mxz),
                    sqrtf(hx*hx + hy*hy + hz*hz));
            }
        }
    }
}

#define MODE_SKIP 1
#define MODE_ZERO 2

// One annealing iteration, warp-autonomous, zero matrix traffic, sorted space.
// Coordinates pre-scaled by sqrt(-l2new) during staging, so the per-pair r2 IS
// the (negated) exp argument: e = 2^(-r2); votes on r2 < 126 (new) / 31.5 (old,
// e_old = e^4). Loop2's sqrt(r2) differs from sqrt(d2) by the constant
// 1/sqrt(-l2new), folded into cons_kernel. Pruning layers (all exact):
// saturated columns (remainR==0), ccrr==0 columns, bounding spheres (original
// space), drained rows (block-wide exit before staging, warp exit after).
template <int MODE>
__global__ void __launch_bounds__(256, 4) passA_kernel(
    float coordScale, float l2old, float sqrtThrN, float sqrtThrO)
{
    __shared__ float4 sm_pt4[MM];        // {sc*x, sc*y, sc*z, remainR}
    __shared__ float  sm_cr[MM];         // ccrr
    __shared__ float4 sm_cbox[NCHUNK];
    __shared__ unsigned char sm_aRR[NCHUNK], sm_aCR[NCHUNK];
    __shared__ float sm_rsum[WPB];

    const int b = blockIdx.y;
    const int t = threadIdx.x, warp = t >> 5, lane = t & 31;
    const int row0 = blockIdx.x * ROWS_PB + warp * RPW;
    const int brow0 = blockIdx.x * ROWS_PB;

    // ---- block-wide early exit: all 32 rows drained => nothing to do --------
    // (drained rows already have g_scaleP == 0 from the iteration that drained
    // them, so no state writes are needed on this path.)
    {
        int drained = 1;
        if (t < ROWS_PB) drained = (g_remainL[b * NN + brow0 + t] == 0.f);
        if (__syncthreads_and(drained)) return;
    }

    // ---- staging: scaled column data + chunk activity masks -----------------
    float rsum = 0.f;
#pragma unroll
    for (int k = 0; k < 8; k++) {
        const int idx = t + 256 * k;
        float4 p = g_xyz2s[b * MM + idx];
        float rrv = g_remainR[b * MM + idx];
        float crv = g_ccrr[b * MM + idx];
        p.x *= coordScale; p.y *= coordScale; p.z *= coordScale;
        p.w = rrv;
        sm_pt4[idx] = p;
        sm_cr[idx] = crv;
        rsum += rrv;
        unsigned mr = __ballot_sync(0xffffffffu, rrv != 0.f);
        unsigned mc = __ballot_sync(0xffffffffu, crv != 0.f);
        if (lane == 0) {
            sm_aRR[warp + 8 * k] = (mr != 0u);
            sm_aCR[warp + 8 * k] = (mc != 0u);
        }
    }
    if (MODE == MODE_ZERO) {
#pragma unroll
        for (int off = 16; off > 0; off >>= 1)
            rsum += __shfl_xor_sync(0xffffffffu, rsum, off);
        if (lane == 0) sm_rsum[warp] = rsum;
    }
    if (t < NCHUNK) sm_cbox[t] = g_cbox[b * NCHUNK + t];
    __syncthreads();

    // ---- row state; warp exit if all rows drained ----------------------------
    float remL[RPW], scP[RPW];
    bool hasPrev = false, allZero = true;
#pragma unroll
    for (int r = 0; r < RPW; r++) {
        remL[r] = g_remainL[b * NN + row0 + r];
        scP[r]  = g_scaleP[b * NN + row0 + r];
        if (scP[r] != 0.f) hasPrev = true;
        if (remL[r] != 0.f) allZero = false;
    }
    if (allZero) return;   // scaleP already 0 for these rows

    float4 rp0 = g_xyz1s[b * NN + row0 + 0];
    float4 rp1 = g_xyz1s[b * NN + row0 + 1];
    float4 rp2 = g_xyz1s[b * NN + row0 + 2];
    float4 rp3 = g_xyz1s[b * NN + row0 + 3];
    const float cs = coordScale;
    const u64 nx01 = pack2(-cs*rp0.x, -cs*rp1.x), nx23 = pack2(-cs*rp2.x, -cs*rp3.x);
    const u64 ny01 = pack2(-cs*rp0.y, -cs*rp1.y), ny23 = pack2(-cs*rp2.y, -cs*rp3.y);
    const u64 nz01 = pack2(-cs*rp0.z, -cs*rp1.z), nz23 = pack2(-cs*rp2.z, -cs*rp3.z);
    const u64 l2o2 = pack2(l2old, l2old);

    // ---- chunk masks: saturation + bounding spheres (original space) --------
    u64 cRR, cCR;
    {
        unsigned lo = __ballot_sync(0xffffffffu, sm_aRR[lane] != 0);
        unsigned hi = __ballot_sync(0xffffffffu, sm_aRR[32 + lane] != 0);
        cRR = ((u64)hi << 32) | lo;
        lo = __ballot_sync(0xffffffffu, sm_aCR[lane] != 0);
        hi = __ballot_sync(0xffffffffu, sm_aCR[32 + lane] != 0);
        cCR = ((u64)hi << 32) | lo;
    }

    u64 boxN = ~0ull, boxO = ~0ull;
    const bool useN = (MODE != MODE_ZERO) && (sqrtThrN < 8.f);
    const bool useO = hasPrev && (sqrtThrO < 8.f);
    if (useN || useO) {
        float mnx = fminf(fminf(rp0.x, rp1.x), fminf(rp2.x, rp3.x));
        float mxx = fmaxf(fmaxf(rp0.x, rp1.x), fmaxf(rp2.x, rp3.x));
        float mny = fminf(fminf(rp0.y, rp1.y), fminf(rp2.y, rp3.y));
        float mxy = fmaxf(fmaxf(rp0.y, rp1.y), fmaxf(rp2.y, rp3.y));
        float mnz = fminf(fminf(rp0.z, rp1.z), fminf(rp2.z, rp3.z));
        float mxz = fmaxf(fmaxf(rp0.z, rp1.z), fmaxf(rp2.z, rp3.z));
        float rcx = 0.5f * (mnx + mxx), hx = 0.5f * (mxx - mnx);
        float rcy = 0.5f * (mny + mxy), hy = 0.5f * (mxy - mny);
        float rcz = 0.5f * (mnz + mxz), hz = 0.5f * (mxz - mnz);
        float Rrow = sqrt_approx(hx*hx + hy*hy + hz*hz) + 0.02f;

        float4 cb = sm_cbox[lane];
        float dx = rcx - cb.x, dy = rcy - cb.y, dz = rcz - cb.z;
        float d2a = dx*dx + dy*dy + dz*dz;
        float limN = cb.w + Rrow + sqrtThrN, limO = cb.w + Rrow + sqrtThrO;
        unsigned loN = __ballot_sync(0xffffffffu, d2a <= limN * limN);
        unsigned loO = __ballot_sync(0xffffffffu, d2a <= limO * limO);
        cb = sm_cbox[32 + lane];
        dx = rcx - cb.x; dy = rcy - cb.y; dz = rcz - cb.z;
        d2a = dx*dx + dy*dy + dz*dz;
        limN = cb.w + Rrow + sqrtThrN; limO = cb.w + Rrow + sqrtThrO;
        unsigned hiN = __ballot_sync(0xffffffffu, d2a <= limN * limN);
        unsigned hiO = __ballot_sync(0xffffffffu, d2a <= limO * limO);
        if (useN) boxN = ((u64)hiN << 32) | loN;
        if (useO) boxO = ((u64)hiO << 32) | loO;
    }

    const u64 maskS = (MODE == MODE_ZERO) ? 0ull : (cRR & boxN);
    const u64 maskR = hasPrev ? (cCR & boxO) : 0ull;
    const u64 maskAny = maskS | maskR;

    u64 srow01 = 0ull, srow23 = 0ull, rdp01 = 0ull, rdp23 = 0ull;  // (0.f,0.f)
    u64 aliveMask = 0ull;

    // ---- loop 1: new-level row sums + old-level deferred decrement ----------
    for (int c = 0; c < MM; c += 32) {
        const int ch = c >> 5;
        if (!((maskAny >> ch) & 1ull)) continue;

        const int col = c + lane;
        const float4 pt = sm_pt4[col];
        const u64 bx2 = pack2(pt.x, pt.x);
        const u64 by2 = pack2(pt.y, pt.y);
        const u64 bz2 = pack2(pt.z, pt.z);

        u64 r201, r223;   // scaled squared distances == negated exp args
        {
            u64 dx = add2(bx2, nx01), dy = add2(by2, ny01), dz = add2(bz2, nz01);
            r201 = fma2(dz, dz, fma2(dy, dy, mul2(dx, dx)));
            dx = add2(bx2, nx23); dy = add2(by2, ny23); dz = add2(bz2, nz23);
            r223 = fma2(dz, dz, fma2(dy, dy, mul2(dx, dx)));
        }

        if (MODE == MODE_ZERO) {
            // rdp-only (maskAny == maskR here); old level direct, coords unscaled
            float b0, b1, b2, b3;
            unpack2(mul2(r201, l2o2), b0, b1);
            unpack2(mul2(r223, l2o2), b2, b3);
            const u64 e01 = pack2(ex2f(b0), ex2f(b1));
            const u64 e23 = pack2(ex2f(b2), ex2f(b3));
            const float lcr = sm_cr[col];
            const u64 lcr2 = pack2(lcr, lcr);
            rdp01 = fma2(e01, lcr2, rdp01);
            rdp23 = fma2(e23, lcr2, rdp23);
        } else {
            const bool bS = (maskS >> ch) & 1ull;
            const bool bR = (maskR >> ch) & 1ull;
            float a0, a1, a2, a3;
            unpack2(r201, a0, a1);
            unpack2(r223, a2, a3);
            float amin = fminf(fminf(a0, a1), fminf(a2, a3));
            const float vthr = bS ? 126.f : 31.5f;   // old arg = 4*new arg
            if (__any_sync(0xffffffffu, amin < vthr)) {
                const u64 e01 = pack2(ex2f_neg(a0), ex2f_neg(a1));
                const u64 e23 = pack2(ex2f_neg(a2), ex2f_neg(a3));
                if (bS) {
                    aliveMask |= 1ull << ch;
                    const u64 lrr2 = pack2(pt.w, pt.w);
                    srow01 = fma2(e01, lrr2, srow01);
                    srow23 = fma2(e23, lrr2, srow23);
                }
                if (bR) {
                    const float lcr = sm_cr[col];
                    const u64 lcr2 = pack2(lcr, lcr);
                    u64 q01 = mul2(e01, e01); q01 = mul2(q01, q01);
                    u64 q23 = mul2(e23, e23); q23 = mul2(q23, q23);
                    rdp01 = fma2(q01, lcr2, rdp01);
                    rdp23 = fma2(q23, lcr2, rdp23);
                }
            }
        }
    }

    float srow[RPW], rdp[RPW];
    unpack2(srow01, srow[0], srow[1]);
    unpack2(srow23, srow[2], srow[3]);
    unpack2(rdp01, rdp[0], rdp[1]);
    unpack2(rdp23, rdp[2], rdp[3]);

    // ---- warp-only reduction (butterfly -> all lanes hold the sums) ---------
#pragma unroll
    for (int off = 16; off > 0; off >>= 1) {
#pragma unroll
        for (int r = 0; r < RPW; r++) {
            rdp[r] += __shfl_xor_sync(0xffffffffu, rdp[r], off);
            if (MODE != MODE_ZERO)
                srow[r] += __shfl_xor_sync(0xffffffffu, srow[r], off);
        }
    }
    if (MODE == MODE_ZERO) {
        float raccT = 0.f;
#pragma unroll
        for (int w = 0; w < WPB; w++) raccT += sm_rsum[w];
#pragma unroll
        for (int r = 0; r < RPW; r++) srow[r] = raccT;
    }

    float scaleEff[RPW];
    bool anyAct = false;
#pragma unroll
    for (int r = 0; r < RPW; r++) {
        const int li = b * NN + row0 + r;
        float rl = fmaxf(remL[r] - scP[r] * rdp[r], 0.f);
        if (rl < 1e-6f) rl = 0.f;          // drained row -> exact zero
        float sc = rl / (srow[r] + EPSv);
        const bool act = (srow[r] != 0.f) && (rl != 0.f);
        scaleEff[r] = act ? sc : 0.f;      // 0 => exact-zero contributions
        if (act) anyAct = true;
        if (lane == 0) {
            g_remainL[li] = rl;
            g_scaleP[li] = act ? sc : 0.f;
        }
    }

    if (!anyAct) return;

    const u64 sc01 = pack2(scaleEff[0], scaleEff[1]);
    const u64 sc23 = pack2(scaleEff[2], scaleEff[3]);
    const u64 ONE2 = pack2(1.f, 1.f);
    const u64 mask2 = (MODE == MODE_ZERO) ? cRR : aliveMask;

    // ---- loop 2: recompute e (bit-identical), scale, column partials --------
    for (int c = 0; c < MM; c += 32) {
        if (!((mask2 >> (c >> 5)) & 1ull)) continue;

        const int col = c + lane;
        const float4 pt = sm_pt4[col];
        const u64 bx2 = pack2(pt.x, pt.x);
        const u64 by2 = pack2(pt.y, pt.y);
        const u64 bz2 = pack2(pt.z, pt.z);

        u64 r201, r223;
        {
            u64 dx = add2(bx2, nx01), dy = add2(by2, ny01), dz = add2(bz2, nz01);
            r201 = fma2(dz, dz, fma2(dy, dy, mul2(dx, dx)));
            dx = add2(bx2, nx23); dy = add2(by2, ny23); dz = add2(bz2, nz23);
            r223 = fma2(dz, dz, fma2(dy, dy, mul2(dx, dx)));
        }

        float a0, a1, a2, a3;
        unpack2(r201, a0, a1);
        unpack2(r223, a2, a3);

        u64 e01, e23;
        if (MODE == MODE_ZERO) {
            e01 = ONE2; e23 = ONE2;
        } else {
            e01 = pack2(ex2f_neg(a0), ex2f_neg(a1));
            e23 = pack2(ex2f_neg(a2), ex2f_neg(a3));
        }

        const u64 lrr2 = pack2(pt.w, pt.w);
        const u64 w01 = mul2(mul2(e01, lrr2), sc01);
        const u64 w23 = mul2(mul2(e23, lrr2), sc23);

        float wl, wh;
        unpack2(add2(w01, w23), wl, wh);
        const float csum = wl + wh;

        // sqrt of SCALED r2; constant 1/sqrt(-l2new) folded into cons_kernel
        const u64 s01 = pack2(sqrt_approx(a0), sqrt_approx(a1));
        const u64 s23 = pack2(sqrt_approx(a2), sqrt_approx(a3));

        float cl, ch2;
        unpack2(fma2(w23, s23, mul2(w01, s01)), cl, ch2);
        const float ccost = cl + ch2;

        red_add_v2(&g_colacc[b * MM + col], csum, ccost);
    }
}

// Column saturation + remainR update + cost accumulation. ccF = 1/sqrt(-l2new)
// converts the scaled-space sqrt back to true sqrt(d2). Saturated columns get
// remainR = exact 0 (enables pruning; true residual ~1e-9*rr).
__global__ void __launch_bounds__(256) cons_kernel(float* __restrict__ out, float ccF) {
    const int b = blockIdx.y;
    const int l = blockIdx.x * 256 + threadIdx.x;
    const int idx = b * MM + l;

    float2 acc = g_colacc[idx];
    float sr  = acc.x;
    float rrv = g_remainR[idx];
    float c = fminf(rrv / (sr + EPSv), 1.0f);
    g_ccrr[idx] = c * rrv;
    g_remainR[idx] = (c < 1.0f) ? 0.f : fmaxf(rrv - sr, 0.f);
    float local = c * acc.y * ccF;
    g_colacc[idx] = make_float2(0.f, 0.f);

#pragma unroll
    for (int off = 16; off > 0; off >>= 1)
        local += __shfl_xor_sync(0xffffffffu, local, off);

    __shared__ float red[8];
    const int warp = threadIdx.x >> 5, lane = threadIdx.x & 31;
    if (lane == 0) red[warp] = local;
    __syncthreads();
    if (threadIdx.x == 0) {
        float s = 0.f;
#pragma unroll
        for (int w = 0; w < 8; w++) s += red[w];
        atomicAdd(&out[b], s);
    }
}

// ---------------------------------------------------------------------------
extern "C" void kernel_launch(void* const* d_in, const int* in_sizes, int n_in,
                              void* d_out, int out_size) {
    (void)in_sizes; (void)n_in; (void)out_size;
    const float* xyz1 = (const float*)d_in[0];
    const float* xyz2 = (const float*)d_in[1];
    float* out = (float*)d_out;

    const float mx = (float)(NN > MM ? NN : MM);
    init_kernel<<<(BB * MM + 255) / 256, 256>>>(out, mx / (float)NN, mx / (float)MM);
    sort_kernel<<<dim3(2, BB), 1024>>>(xyz1, xyz2);

    const float LOG2E = 1.4426950408889634f;
    dim3 grid(NN / ROWS_PB, BB);     // (64, 16) = 1024 blocks
    dim3 cgrid(MM / 256, BB);        // (8, 16) = 128 blocks

    float l2old = 0.f;
    for (int j = 7; j >= -2; --j) {
        float level = (j == -2) ? 0.f : -powf(4.f, (float)j);
        float l2new = level * LOG2E;

        if (j == -2) {
            passA_kernel<MODE_ZERO><<<grid, 256>>>(1.0f, l2old, 1e9f, 1e9f);
            cons_kernel<<<cgrid, 256>>>(out, 1.0f);
        } else {
            float coordScale = sqrtf(-l2new);
            float sqrtThrN = sqrtf(126.f / (-l2new));
            float sqrtThrO = sqrtThrN * 0.5f;   // l2old == 4*l2new
            passA_kernel<MODE_SKIP><<<grid, 256>>>(coordScale, l2old, sqrtThrN, sqrtThrO);
            cons_kernel<<<cgrid, 256>>>(out, 1.0f / coordScale);
        }

        l2old = l2new;
    }
}